// round 13
// baseline (speedup 1.0000x reference)
#include <cuda_runtime.h>
#include <cuda_fp16.h>
#include <cstdint>
#include <math.h>

#define BB 2
#define TT 2048
#define CC 1024
#define HH 16
#define DD 64
#define MM (BB*TT)     // 4096
#define KEXT 2048      // [hi | lo] fp16 extended K (row stride)
#define NIT  64        // KEXT / 32   (final projection)
#define NITQ 32        // 1024 / 32   (QKV projections, hi-only)

// ---------------------------------------------------------------------------
// Scratch (__device__ globals; allocation-free rule)
// ---------------------------------------------------------------------------
__device__ __half g_xe[MM*KEXT];          // x hi (cols 0-1023); attention writes [oh|ol]
__device__ __half g_We[4][CC*KEXT];       // [Wh|Wh] transposed (q,k,v,p)
__device__ __half g_Qe[32*TT*64];         // [bh][t][d] fp16, pre-scaled log2e/8
__device__ __half g_Ke[32*TT*64];         // [bh][t][d] single fp16
__device__ __half g_Ve[32*TT*64];         // [bh][t][d] single fp16

// ---------------------------------------------------------------------------
// PTX helpers (sm_80-era: valid at compute_103)
// ---------------------------------------------------------------------------
__device__ __forceinline__ uint32_t smem_to_u32(const void* p) {
    uint32_t a;
    asm("{ .reg .u64 t; cvta.to.shared.u64 t, %1; cvt.u32.u64 %0, t; }"
        : "=r"(a) : "l"(p));
    return a;
}
__device__ __forceinline__ void cp_async16(uint32_t s, const void* g) {
    asm volatile("cp.async.cg.shared.global [%0], [%1], 16;" :: "r"(s), "l"(g));
}
#define CP_COMMIT() asm volatile("cp.async.commit_group;" ::: "memory")
#define CP_WAIT(n)  asm volatile("cp.async.wait_group %0;" :: "n"(n) : "memory")

__device__ __forceinline__ void ldm_x4(uint32_t addr, uint32_t& r0, uint32_t& r1,
                                       uint32_t& r2, uint32_t& r3) {
    asm volatile("ldmatrix.sync.aligned.m8n8.x4.shared.b16 {%0,%1,%2,%3}, [%4];"
                 : "=r"(r0), "=r"(r1), "=r"(r2), "=r"(r3) : "r"(addr));
}
__device__ __forceinline__ void ldm_x4_t(uint32_t addr, uint32_t& r0, uint32_t& r1,
                                         uint32_t& r2, uint32_t& r3) {
    asm volatile("ldmatrix.sync.aligned.m8n8.x4.trans.shared.b16 {%0,%1,%2,%3}, [%4];"
                 : "=r"(r0), "=r"(r1), "=r"(r2), "=r"(r3) : "r"(addr));
}
__device__ __forceinline__ void mma16816(float* c, const uint32_t* a,
                                         uint32_t b0, uint32_t b1) {
    asm volatile("mma.sync.aligned.m16n8k16.row.col.f32.f16.f16.f32 "
                 "{%0,%1,%2,%3}, {%4,%5,%6,%7}, {%8,%9}, {%0,%1,%2,%3};"
                 : "+f"(c[0]), "+f"(c[1]), "+f"(c[2]), "+f"(c[3])
                 : "r"(a[0]), "r"(a[1]), "r"(a[2]), "r"(a[3]), "r"(b0), "r"(b1));
}
__device__ __forceinline__ float ex2f(float x) {
    float r;
    asm("ex2.approx.ftz.f32 %0, %1;" : "=f"(r) : "f"(x));
    return r;
}
__device__ __forceinline__ void split2h(float v0, float v1, uint32_t& hi, uint32_t& lo) {
    __half2 h = __floats2half2_rn(v0, v1);
    float r0 = v0 - __half2float(__low2half(h));
    float r1 = v1 - __half2float(__high2half(h));
    __half2 l = __floats2half2_rn(r0, r1);
    hi = *(uint32_t*)&h; lo = *(uint32_t*)&l;
}
__device__ __forceinline__ uint32_t pack_h2(float v0, float v1) {
    __half2 h = __floats2half2_rn(v0, v1);
    return *(uint32_t*)&h;
}

// ---------------------------------------------------------------------------
// Prep: fp32 [M,1024] -> fp16 hi into xe cols 0-1023 (rows stride 2048)
// ---------------------------------------------------------------------------
__global__ void convert_a_kernel(const float* __restrict__ X,
                                 __half* __restrict__ Xe)
{
    int idx = blockIdx.x * 256 + threadIdx.x;
    int m  = idx >> 8;
    int c4 = (idx & 255) * 4;
    float4 v = *(const float4*)&X[(size_t)m * CC + c4];
    uint32_t h01 = pack_h2(v.x, v.y);
    uint32_t h23 = pack_h2(v.z, v.w);
    *(uint2*)&Xe[(size_t)m * KEXT + c4] = make_uint2(h01, h23);
}

// ---------------------------------------------------------------------------
// Prep (fused x4): W[K,N] fp32 -> We[N,2048] fp16 = [Wh | Wh] (transposed)
// ---------------------------------------------------------------------------
__global__ void convert_w4_kernel(const float* __restrict__ W0,
                                  const float* __restrict__ W1,
                                  const float* __restrict__ W2,
                                  const float* __restrict__ W3,
                                  __half* __restrict__ We)
{
    __shared__ float tile[32][33];
    const float* W = (blockIdx.z == 0) ? W0 : (blockIdx.z == 1) ? W1
                   : (blockIdx.z == 2) ? W2 : W3;
    __half* dst = We + (size_t)blockIdx.z * CC * KEXT;
    int n0 = blockIdx.x * 32, k0 = blockIdx.y * 32;
    int tx = threadIdx.x, ty = threadIdx.y;
#pragma unroll
    for (int r = 0; r < 4; r++)
        tile[ty + 8*r][tx] = W[(size_t)(k0 + ty + 8*r) * CC + n0 + tx];
    __syncthreads();
#pragma unroll
    for (int r = 0; r < 4; r++) {
        int n = n0 + ty + 8*r;
        int k = k0 + tx;
        __half h = __float2half(tile[tx][ty + 8*r]);
        size_t base = (size_t)n * KEXT;
        dst[base + k]        = h;
        dst[base + 1024 + k] = h;
    }
}

// ---------------------------------------------------------------------------
// Shared GEMM tile machinery (128x128 tile, K-chunk 32, 4-stage cp.async)
// ---------------------------------------------------------------------------
#define ASTRIDE 40
#define TILE_BYTES (128 * ASTRIDE * 2)   // 10240
#define GBUF (2 * TILE_BYTES)            // 20480 per stage
#define GSMEM (4 * GBUF)                 // 81920

struct GemmCtx {
    uint32_t sbase;
    int tid, wid, lane, wm, wn, ldrow, ldc;
    uint32_t a_row, a_col, b_row, b_col;
};
__device__ __forceinline__ void gemm_init(GemmCtx& g, uint32_t sbase) {
    g.tid = threadIdx.x; g.wid = g.tid >> 5; g.lane = g.tid & 31;
    g.sbase = sbase;
    g.wm = (g.wid >> 1) * 32; g.wn = (g.wid & 1) * 64;
    g.ldrow = g.tid >> 2; g.ldc = g.tid & 3;
    g.a_row = g.wm + (g.lane & 15);
    g.a_col = (g.lane >> 4) * 8;
    g.b_row = g.wn + (g.lane & 7) + ((g.lane >> 4) << 3);
    g.b_col = ((g.lane >> 3) & 1) * 8;
}
__device__ __forceinline__ void gemm_issue(const GemmCtx& g, int it,
                                           const __half* A, const __half* B,
                                           int m0, int n0) {
    const int kc = it * 32;
    const uint32_t buf = (it & 3) * GBUF;
#pragma unroll
    for (int r = 0; r < 2; r++) {
        int row = g.ldrow + 64 * r;
        uint32_t sA = g.sbase + buf + row * (ASTRIDE*2) + g.ldc * 16;
        uint32_t sB = sA + TILE_BYTES;
        cp_async16(sA, A + (size_t)(m0 + row) * KEXT + kc + g.ldc * 8);
        cp_async16(sB, B + (size_t)(n0 + row) * KEXT + kc + g.ldc * 8);
    }
    CP_COMMIT();
}
__device__ __forceinline__ void gemm_step(const GemmCtx& g, int it, float acc[2][8][4]) {
    const uint32_t buf = g.sbase + (it & 3) * GBUF;
    const uint32_t bufB = buf + TILE_BYTES;
    uint32_t a[2][2][4];
#pragma unroll
    for (int mi = 0; mi < 2; mi++)
#pragma unroll
        for (int ki = 0; ki < 2; ki++) {
            uint32_t addr = buf + (g.a_row + mi*16) * (ASTRIDE*2) + (ki*16 + g.a_col) * 2;
            ldm_x4(addr, a[mi][ki][0], a[mi][ki][1], a[mi][ki][2], a[mi][ki][3]);
        }
    uint32_t b[2][8][2];
#pragma unroll
    for (int ki = 0; ki < 2; ki++)
#pragma unroll
        for (int nj = 0; nj < 4; nj++) {
            uint32_t addr = bufB + (g.b_row + nj*16) * (ASTRIDE*2) + (ki*16 + g.b_col) * 2;
            uint32_t r0, r1, r2, r3;
            ldm_x4(addr, r0, r1, r2, r3);
            b[ki][2*nj  ][0] = r0; b[ki][2*nj  ][1] = r1;
            b[ki][2*nj+1][0] = r2; b[ki][2*nj+1][1] = r3;
        }
#pragma unroll
    for (int ki = 0; ki < 2; ki++)
#pragma unroll
        for (int mi = 0; mi < 2; mi++)
#pragma unroll
            for (int nj = 0; nj < 8; nj++)
                mma16816(acc[mi][nj], a[mi][ki], b[ki][nj][0], b[ki][nj][1]);
}

// ---------------------------------------------------------------------------
// Fused QKV projection: K=1024 (hi-only A, Wh half of We).
// ---------------------------------------------------------------------------
__global__ __launch_bounds__(256)
void gemm_qkv_kernel(const __half* __restrict__ Ae,
                     const __half* __restrict__ We,
                     const float* __restrict__ bq,
                     const float* __restrict__ bk,
                     const float* __restrict__ bv,
                     __half* __restrict__ qe,
                     __half* __restrict__ ke,
                     __half* __restrict__ ve)
{
    extern __shared__ __align__(16) char smem[];
    const int z = blockIdx.z;
    const __half* Be = We + (size_t)z * CC * KEXT;
    const float* bias = (z == 0) ? bq : (z == 1) ? bk : bv;
    __half* out = (z == 0) ? qe : (z == 1) ? ke : ve;
    // q pre-scaled by log2(e)/8 so attention can use ex2 directly
    const float escale = (z == 0) ? 0.125f * 1.44269504f : 1.0f;
    const int m0 = blockIdx.y * 128, n0 = blockIdx.x * 128;

    GemmCtx g; gemm_init(g, smem_to_u32(smem));
    float acc[2][8][4];
#pragma unroll
    for (int i = 0; i < 2; i++)
#pragma unroll
        for (int j = 0; j < 8; j++)
#pragma unroll
            for (int k = 0; k < 4; k++) acc[i][j][k] = 0.f;

    gemm_issue(g, 0, Ae, Be, m0, n0);
    gemm_issue(g, 1, Ae, Be, m0, n0);
    gemm_issue(g, 2, Ae, Be, m0, n0);
    for (int it = 0; it < NITQ; it++) {
        CP_WAIT(2);
        __syncthreads();
        if (it + 3 < NITQ) gemm_issue(g, it + 3, Ae, Be, m0, n0); else CP_COMMIT();
        gemm_step(g, it, acc);
    }

    const int erow = m0 + g.wm + (g.lane >> 2);
    const int ecol0 = n0 + g.wn + 2 * (g.lane & 3);
#pragma unroll
    for (int mi = 0; mi < 2; mi++)
#pragma unroll
        for (int nj = 0; nj < 8; nj++) {
            int col = ecol0 + nj * 8;
            float bx = bias[col], by = bias[col + 1];
            int r0 = erow + mi * 16;
            int b_ = r0 >> 11, t = r0 & 2047;
            int h  = col >> 6, d = col & 63;
            __half* base = out + ((size_t)((b_ << 4) + h) * TT + t) * 64 + d;
            *(uint32_t*)base =
                pack_h2((acc[mi][nj][0] + bx) * escale, (acc[mi][nj][1] + by) * escale);
            *(uint32_t*)(base + 512) =
                pack_h2((acc[mi][nj][2] + bx) * escale, (acc[mi][nj][3] + by) * escale);
        }
}

// ---------------------------------------------------------------------------
// Output projection: K=2048 ([oh|ol] ext A), fp32 out.
// ---------------------------------------------------------------------------
__global__ __launch_bounds__(256)
void gemm_out_kernel(const __half* __restrict__ Ae,
                     const __half* __restrict__ Be,
                     const float* __restrict__ bias,
                     float* __restrict__ Cout)
{
    extern __shared__ __align__(16) char smem[];
    const int m0 = blockIdx.y * 128, n0 = blockIdx.x * 128;

    GemmCtx g; gemm_init(g, smem_to_u32(smem));
    float acc[2][8][4];
#pragma unroll
    for (int i = 0; i < 2; i++)
#pragma unroll
        for (int j = 0; j < 8; j++)
#pragma unroll
            for (int k = 0; k < 4; k++) acc[i][j][k] = 0.f;

    gemm_issue(g, 0, Ae, Be, m0, n0);
    gemm_issue(g, 1, Ae, Be, m0, n0);
    gemm_issue(g, 2, Ae, Be, m0, n0);
    for (int it = 0; it < NIT; it++) {
        CP_WAIT(2);
        __syncthreads();
        if (it + 3 < NIT) gemm_issue(g, it + 3, Ae, Be, m0, n0); else CP_COMMIT();
        gemm_step(g, it, acc);
    }

    const int erow = m0 + g.wm + (g.lane >> 2);
    const int ecol0 = n0 + g.wn + 2 * (g.lane & 3);
#pragma unroll
    for (int mi = 0; mi < 2; mi++)
#pragma unroll
        for (int nj = 0; nj < 8; nj++) {
            int col = ecol0 + nj * 8;
            float bx = bias[col], by = bias[col + 1];
            int r0 = erow + mi * 16;
            *(float2*)&Cout[(size_t)r0 * CC + col] =
                make_float2(acc[mi][nj][0] + bx, acc[mi][nj][1] + by);
            *(float2*)&Cout[(size_t)(r0 + 8) * CC + col] =
                make_float2(acc[mi][nj][2] + bx, acc[mi][nj][3] + by);
        }
}

// ---------------------------------------------------------------------------
// MMA flash attention: 4 warps x 32 query rows; Q persistent in smem;
// per-mi, per-2-keygroup fused pipeline (regs <= ~130); 4 CTA/SM single wave.
// grid (T/128, B*H), 128 threads.
// ---------------------------------------------------------------------------
#define KSTR2 144                 // Q/K/V smem row stride bytes (64 fp16 + pad)
#define ATQ_SZ (128 * KSTR2)      // 18432 (persistent Q tile)
#define AT_VOFF (64 * KSTR2)      // 9216
#define AT_BUF  (2 * 64 * KSTR2)  // 18432 per KV buffer
#define AT_SMEM (ATQ_SZ + 2 * AT_BUF)  // 55296 (dynamic)

__global__ __launch_bounds__(128, 4)
void attn_mma_kernel(const __half* __restrict__ Qe,
                     const __half* __restrict__ Ke,
                     const __half* __restrict__ Ve,
                     __half* __restrict__ oe)
{
    extern __shared__ __align__(16) char smem[];
    const uint32_t sbase = smem_to_u32(smem);
    const uint32_t kvbase = sbase + ATQ_SZ;
    const int tid  = threadIdx.x;
    const int wid  = tid >> 5;
    const int lane = tid & 31;
    const int qb   = blockIdx.x;
    const int bh   = blockIdx.y;
    const int wm   = wid * 32;          // 32 query rows per warp

    const __half* Qg = Qe + ((size_t)bh * TT + qb * 128) * 64;
    const __half* Kg = Ke + (size_t)bh * TT * 64;
    const __half* Vg = Ve + (size_t)bh * TT * 64;

    // --- stage Q tile into its persistent region ---
#pragma unroll
    for (int i = 0; i < 8; i++) {
        int idx = tid + 128 * i;           // 0..1023
        int row = idx >> 3, c = idx & 7;
        cp_async16(sbase + row * KSTR2 + c * 16, Qg + (size_t)row * 64 + c * 8);
    }
    CP_COMMIT();

    auto issue = [&](int kt) {
        const uint32_t buf = kvbase + (kt & 1) * AT_BUF;
        const int r0 = kt * 64;
#pragma unroll
        for (int i = 0; i < 4; i++) {
            int idx = tid + 128 * i;       // 0..511 (64 rows x 8 chunks)
            int row = idx >> 3, c = idx & 7;
            cp_async16(buf + row * KSTR2 + c * 16, Kg + (size_t)(r0 + row) * 64 + c * 8);
            cp_async16(buf + AT_VOFF + row * KSTR2 + c * 16, Vg + (size_t)(r0 + row) * 64 + c * 8);
        }
        CP_COMMIT();
    };

    float oacc[2][8][4];
#pragma unroll
    for (int mi = 0; mi < 2; mi++)
#pragma unroll
        for (int j = 0; j < 8; j++)
#pragma unroll
            for (int k = 0; k < 4; k++) oacc[mi][j][k] = 0.f;
    float lsum[2][2] = {{0.f, 0.f}, {0.f, 0.f}};

    const uint32_t frow_off = ((lane & 7) + ((lane >> 3) & 1) * 8) * KSTR2;
    const uint32_t fcol_off = ((lane >> 4) * 8) * 2;
    // Q frag base address (per mi add mi*16*KSTR2)
    const uint32_t qfrag = sbase + (wm + (lane & 15)) * KSTR2 + ((lane >> 4) * 8) * 2;

    issue(0);
    for (int it = 0; it < TT / 64; it++) {
        if (it + 1 < TT / 64) { issue(it + 1); CP_WAIT(1); }
        else                  { CP_WAIT(0); }
        __syncthreads();
        const uint32_t kb = kvbase + (it & 1) * AT_BUF + frow_off + fcol_off;
        const uint32_t vb = kb + AT_VOFF;

        // per 16-row half (mi), per 2-keygroup chunk (gh): S -> exp -> PV
#pragma unroll
        for (int mi = 0; mi < 2; mi++) {
            uint32_t aq[4][4];
#pragma unroll
            for (int c = 0; c < 4; c++)
                ldm_x4(qfrag + mi * (16 * KSTR2) + c * 32,
                       aq[c][0], aq[c][1], aq[c][2], aq[c][3]);

#pragma unroll
            for (int gh = 0; gh < 2; gh++) {
                const uint32_t g0row = kb + (gh * 2)     * (16 * KSTR2);
                const uint32_t g1row = kb + (gh * 2 + 1) * (16 * KSTR2);

                float s[4][4];
#pragma unroll
                for (int j = 0; j < 4; j++)
#pragma unroll
                    for (int k = 0; k < 4; k++) s[j][k] = 0.f;

#pragma unroll
                for (int c = 0; c < 4; c++) {
                    uint32_t r0, r1, r2, r3;
                    ldm_x4(g0row + c * 32, r0, r1, r2, r3);
                    mma16816(s[0], aq[c], r0, r2);
                    mma16816(s[1], aq[c], r1, r3);
                    ldm_x4(g1row + c * 32, r0, r1, r2, r3);
                    mma16816(s[2], aq[c], r0, r2);
                    mma16816(s[3], aq[c], r1, r3);
                }

                uint32_t ph[2][4];
#pragma unroll
                for (int gg = 0; gg < 2; gg++) {
                    float e0 = ex2f(s[2*gg][0]),   e1 = ex2f(s[2*gg][1]);
                    float e2 = ex2f(s[2*gg][2]),   e3 = ex2f(s[2*gg][3]);
                    float e4 = ex2f(s[2*gg+1][0]), e5 = ex2f(s[2*gg+1][1]);
                    float e6 = ex2f(s[2*gg+1][2]), e7 = ex2f(s[2*gg+1][3]);
                    lsum[mi][0] += e0 + e1 + e4 + e5;
                    lsum[mi][1] += e2 + e3 + e6 + e7;
                    ph[gg][0] = pack_h2(e0, e1);
                    ph[gg][1] = pack_h2(e2, e3);
                    ph[gg][2] = pack_h2(e4, e5);
                    ph[gg][3] = pack_h2(e6, e7);
                }

                // PV for these 2 key groups
#pragma unroll
                for (int gg = 0; gg < 2; gg++) {
                    uint32_t vrb = vb + (gh * 2 + gg) * (16 * KSTR2);
#pragma unroll
                    for (int ng = 0; ng < 4; ng++) {
                        uint32_t r0, r1, r2, r3;
                        ldm_x4_t(vrb + ng * 32, r0, r1, r2, r3);
                        mma16816(oacc[mi][2*ng],   ph[gg], r0, r1);
                        mma16816(oacc[mi][2*ng+1], ph[gg], r2, r3);
                    }
                }
            }
        }
        __syncthreads();
    }

    // ---- normalize + write [oh | ol] ext rows into oe [M, 2048] ----
    int b_ = bh >> 4, h = bh & 15;
    int colb = h * 64 + 2 * (lane & 3);
#pragma unroll
    for (int mi = 0; mi < 2; mi++) {
        float l0 = lsum[mi][0], l1 = lsum[mi][1];
        l0 += __shfl_xor_sync(0xFFFFFFFF, l0, 1);
        l0 += __shfl_xor_sync(0xFFFFFFFF, l0, 2);
        l1 += __shfl_xor_sync(0xFFFFFFFF, l1, 1);
        l1 += __shfl_xor_sync(0xFFFFFFFF, l1, 2);
        float inv0 = 1.f / l0, inv1 = 1.f / l1;

        int t0 = qb * 128 + wm + mi * 16 + (lane >> 2);
        size_t m = (size_t)b_ * TT + t0;
#pragma unroll
        for (int nj = 0; nj < 8; nj++) {
            int col = colb + nj * 8;
            uint32_t hi, lo;
            __half* base = oe + m * KEXT + col;
            split2h(oacc[mi][nj][0] * inv0, oacc[mi][nj][1] * inv0, hi, lo);
            *(uint32_t*)base = hi; *(uint32_t*)(base + 1024) = lo;
            base += (size_t)8 * KEXT;
            split2h(oacc[mi][nj][2] * inv1, oacc[mi][nj][3] * inv1, hi, lo);
            *(uint32_t*)base = hi; *(uint32_t*)(base + 1024) = lo;
        }
    }
}

// ---------------------------------------------------------------------------
extern "C" void kernel_launch(void* const* d_in, const int* in_sizes, int n_in,
                              void* d_out, int out_size)
{
    const float* x  = (const float*)d_in[0];
    const float* Wq = (const float*)d_in[2];
    const float* bq = (const float*)d_in[3];
    const float* Wk = (const float*)d_in[4];
    const float* bk = (const float*)d_in[5];
    const float* Wv = (const float*)d_in[6];
    const float* bv = (const float*)d_in[7];
    const float* Wp = (const float*)d_in[8];
    const float* bp = (const float*)d_in[9];
    float* out = (float*)d_out;

    __half *xe, *we, *qe, *ke, *ve;
    cudaGetSymbolAddress((void**)&xe, g_xe);
    cudaGetSymbolAddress((void**)&we, g_We);
    cudaGetSymbolAddress((void**)&qe, g_Qe);
    cudaGetSymbolAddress((void**)&ke, g_Ke);
    cudaGetSymbolAddress((void**)&ve, g_Ve);
    __half* wpe = we + (size_t)3 * CC * KEXT;

    cudaFuncSetAttribute(gemm_qkv_kernel,
                         cudaFuncAttributeMaxDynamicSharedMemorySize, GSMEM);
    cudaFuncSetAttribute(gemm_out_kernel,
                         cudaFuncAttributeMaxDynamicSharedMemorySize, GSMEM);
    cudaFuncSetAttribute(attn_mma_kernel,
                         cudaFuncAttributeMaxDynamicSharedMemorySize, AT_SMEM);

    // prep
    convert_a_kernel<<<MM, 256>>>(x, xe);
    dim3 wgrd(CC / 32, CC / 32, 4), wblk(32, 8);
    convert_w4_kernel<<<wgrd, wblk>>>(Wq, Wk, Wv, Wp, we);

    // fused QKV projections (K=1024, hi-only)
    dim3 qgrd(CC / 128, MM / 128, 3);  // (8, 32, 3)
    gemm_qkv_kernel<<<qgrd, 256, GSMEM>>>(xe, we, bq, bk, bv, qe, ke, ve);

    // attention (writes [oh|ol] ext layout into xe)
    dim3 agrd(TT / 128, BB * HH);
    attn_mma_kernel<<<agrd, 128, AT_SMEM>>>(qe, ke, ve, xe);

    // output projection (K=2048)
    dim3 ggrd(CC / 128, MM / 128);  // (8, 32)
    gemm_out_kernel<<<ggrd, 256, GSMEM>>>(xe, wpe, bp, out);
}

// round 14
// speedup vs baseline: 1.2487x; 1.2487x over previous
#include <cuda_runtime.h>
#include <cuda_fp16.h>
#include <cstdint>
#include <math.h>

#define BB 2
#define TT 2048
#define CC 1024
#define HH 16
#define DD 64
#define MM (BB*TT)     // 4096
#define KEXT 2048      // [hi | lo] fp16 extended K (row stride)
#define NIT  32        // KEXT / 64   (final projection)
#define NITQ 16        // 1024 / 64   (QKV projections, hi-only)

// ---------------------------------------------------------------------------
// Scratch (__device__ globals; allocation-free rule)
// ---------------------------------------------------------------------------
__device__ __half g_xe[MM*KEXT];          // x hi (cols 0-1023); attention writes [oh|ol]
__device__ __half g_We[4][CC*KEXT];       // [Wh|Wh] transposed (q,k,v,p)
__device__ __half g_Qe[32*TT*64];         // [bh][t][d] fp16, pre-scaled log2e/8
__device__ __half g_Ke[32*TT*64];         // [bh][t][d] single fp16
__device__ __half g_Ve[32*TT*64];         // [bh][t][d] single fp16

// ---------------------------------------------------------------------------
// PTX helpers (sm_80-era: valid at compute_103)
// ---------------------------------------------------------------------------
__device__ __forceinline__ uint32_t smem_to_u32(const void* p) {
    uint32_t a;
    asm("{ .reg .u64 t; cvta.to.shared.u64 t, %1; cvt.u32.u64 %0, t; }"
        : "=r"(a) : "l"(p));
    return a;
}
__device__ __forceinline__ void cp_async16(uint32_t s, const void* g) {
    asm volatile("cp.async.cg.shared.global [%0], [%1], 16;" :: "r"(s), "l"(g));
}
#define CP_COMMIT() asm volatile("cp.async.commit_group;" ::: "memory")
#define CP_WAIT(n)  asm volatile("cp.async.wait_group %0;" :: "n"(n) : "memory")

__device__ __forceinline__ void ldm_x4(uint32_t addr, uint32_t& r0, uint32_t& r1,
                                       uint32_t& r2, uint32_t& r3) {
    asm volatile("ldmatrix.sync.aligned.m8n8.x4.shared.b16 {%0,%1,%2,%3}, [%4];"
                 : "=r"(r0), "=r"(r1), "=r"(r2), "=r"(r3) : "r"(addr));
}
__device__ __forceinline__ void ldm_x4_t(uint32_t addr, uint32_t& r0, uint32_t& r1,
                                         uint32_t& r2, uint32_t& r3) {
    asm volatile("ldmatrix.sync.aligned.m8n8.x4.trans.shared.b16 {%0,%1,%2,%3}, [%4];"
                 : "=r"(r0), "=r"(r1), "=r"(r2), "=r"(r3) : "r"(addr));
}
__device__ __forceinline__ void mma16816(float* c, const uint32_t* a,
                                         uint32_t b0, uint32_t b1) {
    asm volatile("mma.sync.aligned.m16n8k16.row.col.f32.f16.f16.f32 "
                 "{%0,%1,%2,%3}, {%4,%5,%6,%7}, {%8,%9}, {%0,%1,%2,%3};"
                 : "+f"(c[0]), "+f"(c[1]), "+f"(c[2]), "+f"(c[3])
                 : "r"(a[0]), "r"(a[1]), "r"(a[2]), "r"(a[3]), "r"(b0), "r"(b1));
}
__device__ __forceinline__ float ex2f(float x) {
    float r;
    asm("ex2.approx.ftz.f32 %0, %1;" : "=f"(r) : "f"(x));
    return r;
}
__device__ __forceinline__ void split2h(float v0, float v1, uint32_t& hi, uint32_t& lo) {
    __half2 h = __floats2half2_rn(v0, v1);
    float r0 = v0 - __half2float(__low2half(h));
    float r1 = v1 - __half2float(__high2half(h));
    __half2 l = __floats2half2_rn(r0, r1);
    hi = *(uint32_t*)&h; lo = *(uint32_t*)&l;
}
__device__ __forceinline__ uint32_t pack_h2(float v0, float v1) {
    __half2 h = __floats2half2_rn(v0, v1);
    return *(uint32_t*)&h;
}

// ---------------------------------------------------------------------------
// Prep: fp32 [M,1024] -> fp16 hi into xe cols 0-1023 (rows stride 2048)
// ---------------------------------------------------------------------------
__global__ void convert_a_kernel(const float* __restrict__ X,
                                 __half* __restrict__ Xe)
{
    int idx = blockIdx.x * 256 + threadIdx.x;
    int m  = idx >> 8;
    int c4 = (idx & 255) * 4;
    float4 v = *(const float4*)&X[(size_t)m * CC + c4];
    uint32_t h01 = pack_h2(v.x, v.y);
    uint32_t h23 = pack_h2(v.z, v.w);
    *(uint2*)&Xe[(size_t)m * KEXT + c4] = make_uint2(h01, h23);
}

// ---------------------------------------------------------------------------
// Prep (fused x4): W[K,N] fp32 -> We[N,2048] fp16 = [Wh | Wh] (transposed)
// ---------------------------------------------------------------------------
__global__ void convert_w4_kernel(const float* __restrict__ W0,
                                  const float* __restrict__ W1,
                                  const float* __restrict__ W2,
                                  const float* __restrict__ W3,
                                  __half* __restrict__ We)
{
    __shared__ float tile[32][33];
    const float* W = (blockIdx.z == 0) ? W0 : (blockIdx.z == 1) ? W1
                   : (blockIdx.z == 2) ? W2 : W3;
    __half* dst = We + (size_t)blockIdx.z * CC * KEXT;
    int n0 = blockIdx.x * 32, k0 = blockIdx.y * 32;
    int tx = threadIdx.x, ty = threadIdx.y;
#pragma unroll
    for (int r = 0; r < 4; r++)
        tile[ty + 8*r][tx] = W[(size_t)(k0 + ty + 8*r) * CC + n0 + tx];
    __syncthreads();
#pragma unroll
    for (int r = 0; r < 4; r++) {
        int n = n0 + ty + 8*r;
        int k = k0 + tx;
        __half h = __float2half(tile[tx][ty + 8*r]);
        size_t base = (size_t)n * KEXT;
        dst[base + k]        = h;
        dst[base + 1024 + k] = h;
    }
}

// ---------------------------------------------------------------------------
// GEMM machinery: 128x128 tile, K-chunk 64, 3-stage cp.async pipeline.
// Row stride 72 fp16 (144B) -> conflict-free ldmatrix.
// ---------------------------------------------------------------------------
#define GROWB 144                        // smem row bytes (64 fp16 + 8 pad)
#define TILE_BYTES (128 * GROWB)         // 18432 per operand
#define GBUF (2 * TILE_BYTES)            // 36864 per stage
#define GSMEM (3 * GBUF)                 // 110592

struct GemmCtx {
    uint32_t sbase;
    int tid, wid, lane, wm, wn;
    uint32_t a_row, a_col, b_row, b_col;
};
__device__ __forceinline__ void gemm_init(GemmCtx& g, uint32_t sbase) {
    g.tid = threadIdx.x; g.wid = g.tid >> 5; g.lane = g.tid & 31;
    g.sbase = sbase;
    g.wm = (g.wid >> 1) * 32; g.wn = (g.wid & 1) * 64;
    g.a_row = g.wm + (g.lane & 15);
    g.a_col = (g.lane >> 4) * 8;
    g.b_row = g.wn + (g.lane & 7) + ((g.lane >> 4) << 3);
    g.b_col = ((g.lane >> 3) & 1) * 8;
}
__device__ __forceinline__ void gemm_issue(const GemmCtx& g, int it,
                                           const __half* A, const __half* B,
                                           int m0, int n0) {
    const int kc = it * 64;
    const uint32_t buf = g.sbase + (it % 3) * GBUF;
#pragma unroll
    for (int i = 0; i < 4; i++) {
        int idx = g.tid + 256 * i;          // 0..1023
        int row = idx >> 3, c = idx & 7;    // 128 rows x 8 chunks
        cp_async16(buf + row * GROWB + c * 16,
                   A + (size_t)(m0 + row) * KEXT + kc + c * 8);
        cp_async16(buf + TILE_BYTES + row * GROWB + c * 16,
                   B + (size_t)(n0 + row) * KEXT + kc + c * 8);
    }
    CP_COMMIT();
}
__device__ __forceinline__ void gemm_step(const GemmCtx& g, int it, float acc[2][8][4]) {
    const uint32_t buf = g.sbase + (it % 3) * GBUF;
    const uint32_t bufB = buf + TILE_BYTES;
#pragma unroll
    for (int ki = 0; ki < 4; ki++) {
        uint32_t a[2][4];
#pragma unroll
        for (int mi = 0; mi < 2; mi++) {
            uint32_t addr = buf + (g.a_row + mi*16) * GROWB + (ki*16 + g.a_col) * 2;
            ldm_x4(addr, a[mi][0], a[mi][1], a[mi][2], a[mi][3]);
        }
        uint32_t b[8][2];
#pragma unroll
        for (int nj = 0; nj < 4; nj++) {
            uint32_t addr = bufB + (g.b_row + nj*16) * GROWB + (ki*16 + g.b_col) * 2;
            uint32_t r0, r1, r2, r3;
            ldm_x4(addr, r0, r1, r2, r3);
            b[2*nj  ][0] = r0; b[2*nj  ][1] = r1;
            b[2*nj+1][0] = r2; b[2*nj+1][1] = r3;
        }
#pragma unroll
        for (int mi = 0; mi < 2; mi++)
#pragma unroll
            for (int nj = 0; nj < 8; nj++)
                mma16816(acc[mi][nj], a[mi], b[nj][0], b[nj][1]);
    }
}

// ---------------------------------------------------------------------------
// Fused QKV projection: K=1024 (hi-only A, Wh half of We).
// ---------------------------------------------------------------------------
__global__ __launch_bounds__(256)
void gemm_qkv_kernel(const __half* __restrict__ Ae,
                     const __half* __restrict__ We,
                     const float* __restrict__ bq,
                     const float* __restrict__ bk,
                     const float* __restrict__ bv,
                     __half* __restrict__ qe,
                     __half* __restrict__ ke,
                     __half* __restrict__ ve)
{
    extern __shared__ __align__(16) char smem[];
    const int z = blockIdx.z;
    const __half* Be = We + (size_t)z * CC * KEXT;
    const float* bias = (z == 0) ? bq : (z == 1) ? bk : bv;
    __half* out = (z == 0) ? qe : (z == 1) ? ke : ve;
    // q pre-scaled by log2(e)/8 so attention can use ex2 directly
    const float escale = (z == 0) ? 0.125f * 1.44269504f : 1.0f;
    const int m0 = blockIdx.y * 128, n0 = blockIdx.x * 128;

    GemmCtx g; gemm_init(g, smem_to_u32(smem));
    float acc[2][8][4];
#pragma unroll
    for (int i = 0; i < 2; i++)
#pragma unroll
        for (int j = 0; j < 8; j++)
#pragma unroll
            for (int k = 0; k < 4; k++) acc[i][j][k] = 0.f;

    gemm_issue(g, 0, Ae, Be, m0, n0);
    gemm_issue(g, 1, Ae, Be, m0, n0);
    for (int it = 0; it < NITQ; it++) {
        CP_WAIT(1);
        __syncthreads();
        if (it + 2 < NITQ) gemm_issue(g, it + 2, Ae, Be, m0, n0); else CP_COMMIT();
        gemm_step(g, it, acc);
    }

    const int erow = m0 + g.wm + (g.lane >> 2);
    const int ecol0 = n0 + g.wn + 2 * (g.lane & 3);
#pragma unroll
    for (int mi = 0; mi < 2; mi++)
#pragma unroll
        for (int nj = 0; nj < 8; nj++) {
            int col = ecol0 + nj * 8;
            float bx = bias[col], by = bias[col + 1];
            int r0 = erow + mi * 16;
            int b_ = r0 >> 11, t = r0 & 2047;
            int h  = col >> 6, d = col & 63;
            __half* base = out + ((size_t)((b_ << 4) + h) * TT + t) * 64 + d;
            *(uint32_t*)base =
                pack_h2((acc[mi][nj][0] + bx) * escale, (acc[mi][nj][1] + by) * escale);
            *(uint32_t*)(base + 512) =
                pack_h2((acc[mi][nj][2] + bx) * escale, (acc[mi][nj][3] + by) * escale);
        }
}

// ---------------------------------------------------------------------------
// Output projection: K=2048 ([oh|ol] ext A), fp32 out.
// ---------------------------------------------------------------------------
__global__ __launch_bounds__(256)
void gemm_out_kernel(const __half* __restrict__ Ae,
                     const __half* __restrict__ Be,
                     const float* __restrict__ bias,
                     float* __restrict__ Cout)
{
    extern __shared__ __align__(16) char smem[];
    const int m0 = blockIdx.y * 128, n0 = blockIdx.x * 128;

    GemmCtx g; gemm_init(g, smem_to_u32(smem));
    float acc[2][8][4];
#pragma unroll
    for (int i = 0; i < 2; i++)
#pragma unroll
        for (int j = 0; j < 8; j++)
#pragma unroll
            for (int k = 0; k < 4; k++) acc[i][j][k] = 0.f;

    gemm_issue(g, 0, Ae, Be, m0, n0);
    gemm_issue(g, 1, Ae, Be, m0, n0);
    for (int it = 0; it < NIT; it++) {
        CP_WAIT(1);
        __syncthreads();
        if (it + 2 < NIT) gemm_issue(g, it + 2, Ae, Be, m0, n0); else CP_COMMIT();
        gemm_step(g, it, acc);
    }

    const int erow = m0 + g.wm + (g.lane >> 2);
    const int ecol0 = n0 + g.wn + 2 * (g.lane & 3);
#pragma unroll
    for (int mi = 0; mi < 2; mi++)
#pragma unroll
        for (int nj = 0; nj < 8; nj++) {
            int col = ecol0 + nj * 8;
            float bx = bias[col], by = bias[col + 1];
            int r0 = erow + mi * 16;
            *(float2*)&Cout[(size_t)r0 * CC + col] =
                make_float2(acc[mi][nj][0] + bx, acc[mi][nj][1] + by);
            *(float2*)&Cout[(size_t)(r0 + 8) * CC + col] =
                make_float2(acc[mi][nj][2] + bx, acc[mi][nj][3] + by);
        }
}

// ---------------------------------------------------------------------------
// MMA flash attention (R11 proven config): 4 warps x 32 query rows;
// Q persistent in smem; S phase split by 16-row half; wide-S dataflow.
// grid (T/128, B*H), 128 threads, 3 CTA/SM.
// ---------------------------------------------------------------------------
#define KSTR2 144                 // Q/K/V smem row stride bytes (64 fp16 + pad)
#define ATQ_SZ (128 * KSTR2)      // 18432 (persistent Q tile)
#define AT_VOFF (64 * KSTR2)      // 9216
#define AT_BUF  (2 * 64 * KSTR2)  // 18432 per KV buffer
#define AT_SMEM (ATQ_SZ + 2 * AT_BUF)  // 55296 (dynamic)

__global__ __launch_bounds__(128, 3)
void attn_mma_kernel(const __half* __restrict__ Qe,
                     const __half* __restrict__ Ke,
                     const __half* __restrict__ Ve,
                     __half* __restrict__ oe)
{
    extern __shared__ __align__(16) char smem[];
    const uint32_t sbase = smem_to_u32(smem);
    const uint32_t kvbase = sbase + ATQ_SZ;
    const int tid  = threadIdx.x;
    const int wid  = tid >> 5;
    const int lane = tid & 31;
    const int qb   = blockIdx.x;
    const int bh   = blockIdx.y;
    const int wm   = wid * 32;          // 32 query rows per warp

    const __half* Qg = Qe + ((size_t)bh * TT + qb * 128) * 64;
    const __half* Kg = Ke + (size_t)bh * TT * 64;
    const __half* Vg = Ve + (size_t)bh * TT * 64;

    // --- stage Q tile into its persistent region ---
#pragma unroll
    for (int i = 0; i < 8; i++) {
        int idx = tid + 128 * i;           // 0..1023
        int row = idx >> 3, c = idx & 7;
        cp_async16(sbase + row * KSTR2 + c * 16, Qg + (size_t)row * 64 + c * 8);
    }
    CP_COMMIT();

    auto issue = [&](int kt) {
        const uint32_t buf = kvbase + (kt & 1) * AT_BUF;
        const int r0 = kt * 64;
#pragma unroll
        for (int i = 0; i < 4; i++) {
            int idx = tid + 128 * i;       // 0..511 (64 rows x 8 chunks)
            int row = idx >> 3, c = idx & 7;
            cp_async16(buf + row * KSTR2 + c * 16, Kg + (size_t)(r0 + row) * 64 + c * 8);
            cp_async16(buf + AT_VOFF + row * KSTR2 + c * 16, Vg + (size_t)(r0 + row) * 64 + c * 8);
        }
        CP_COMMIT();
    };

    float oacc[2][8][4];
#pragma unroll
    for (int mi = 0; mi < 2; mi++)
#pragma unroll
        for (int j = 0; j < 8; j++)
#pragma unroll
            for (int k = 0; k < 4; k++) oacc[mi][j][k] = 0.f;
    float lsum[2][2] = {{0.f, 0.f}, {0.f, 0.f}};

    const uint32_t frow_off = ((lane & 7) + ((lane >> 3) & 1) * 8) * KSTR2;
    const uint32_t fcol_off = ((lane >> 4) * 8) * 2;
    // Q frag base address (per mi add mi*16*KSTR2)
    const uint32_t qfrag = sbase + (wm + (lane & 15)) * KSTR2 + ((lane >> 4) * 8) * 2;

    issue(0);
    for (int it = 0; it < TT / 64; it++) {
        if (it + 1 < TT / 64) { issue(it + 1); CP_WAIT(1); }
        else                  { CP_WAIT(0); }
        __syncthreads();
        const uint32_t kb = kvbase + (it & 1) * AT_BUF + frow_off + fcol_off;
        const uint32_t vb = kb + AT_VOFF;

        uint32_t ph[2][4][4];
        // ---- S + exp, one 16-row half at a time (register diet) ----
#pragma unroll
        for (int mi = 0; mi < 2; mi++) {
            uint32_t aq[4][4];
#pragma unroll
            for (int c = 0; c < 4; c++)
                ldm_x4(qfrag + mi * (16 * KSTR2) + c * 32,
                       aq[c][0], aq[c][1], aq[c][2], aq[c][3]);

            float s[8][4];
#pragma unroll
            for (int j = 0; j < 8; j++)
#pragma unroll
                for (int k = 0; k < 4; k++) s[j][k] = 0.f;

#pragma unroll
            for (int g = 0; g < 4; g++) {
                uint32_t grow = kb + g * (16 * KSTR2);
#pragma unroll
                for (int c = 0; c < 4; c++) {
                    uint32_t r0, r1, r2, r3;
                    ldm_x4(grow + c * 32, r0, r1, r2, r3);
                    mma16816(s[2*g],   aq[c], r0, r2);
                    mma16816(s[2*g+1], aq[c], r1, r3);
                }
            }

#pragma unroll
            for (int g = 0; g < 4; g++) {
                float e0 = ex2f(s[2*g][0]),   e1 = ex2f(s[2*g][1]);
                float e2 = ex2f(s[2*g][2]),   e3 = ex2f(s[2*g][3]);
                float e4 = ex2f(s[2*g+1][0]), e5 = ex2f(s[2*g+1][1]);
                float e6 = ex2f(s[2*g+1][2]), e7 = ex2f(s[2*g+1][3]);
                lsum[mi][0] += e0 + e1 + e4 + e5;
                lsum[mi][1] += e2 + e3 + e6 + e7;
                ph[mi][g][0] = pack_h2(e0, e1);
                ph[mi][g][1] = pack_h2(e2, e3);
                ph[mi][g][2] = pack_h2(e4, e5);
                ph[mi][g][3] = pack_h2(e6, e7);
            }
        }

        // ---- O += p . v (both halves) ----
#pragma unroll
        for (int g = 0; g < 4; g++) {
            uint32_t vrb = vb + g * (16 * KSTR2);
#pragma unroll
            for (int ng = 0; ng < 4; ng++) {
                uint32_t r0, r1, r2, r3;
                ldm_x4_t(vrb + ng * 32, r0, r1, r2, r3);
#pragma unroll
                for (int mi = 0; mi < 2; mi++) {
                    mma16816(oacc[mi][2*ng],   ph[mi][g], r0, r1);
                    mma16816(oacc[mi][2*ng+1], ph[mi][g], r2, r3);
                }
            }
        }
        __syncthreads();
    }

    // ---- normalize + write [oh | ol] ext rows into oe [M, 2048] ----
    int b_ = bh >> 4, h = bh & 15;
    int colb = h * 64 + 2 * (lane & 3);
#pragma unroll
    for (int mi = 0; mi < 2; mi++) {
        float l0 = lsum[mi][0], l1 = lsum[mi][1];
        l0 += __shfl_xor_sync(0xFFFFFFFF, l0, 1);
        l0 += __shfl_xor_sync(0xFFFFFFFF, l0, 2);
        l1 += __shfl_xor_sync(0xFFFFFFFF, l1, 1);
        l1 += __shfl_xor_sync(0xFFFFFFFF, l1, 2);
        float inv0 = 1.f / l0, inv1 = 1.f / l1;

        int t0 = qb * 128 + wm + mi * 16 + (lane >> 2);
        size_t m = (size_t)b_ * TT + t0;
#pragma unroll
        for (int nj = 0; nj < 8; nj++) {
            int col = colb + nj * 8;
            uint32_t hi, lo;
            __half* base = oe + m * KEXT + col;
            split2h(oacc[mi][nj][0] * inv0, oacc[mi][nj][1] * inv0, hi, lo);
            *(uint32_t*)base = hi; *(uint32_t*)(base + 1024) = lo;
            base += (size_t)8 * KEXT;
            split2h(oacc[mi][nj][2] * inv1, oacc[mi][nj][3] * inv1, hi, lo);
            *(uint32_t*)base = hi; *(uint32_t*)(base + 1024) = lo;
        }
    }
}

// ---------------------------------------------------------------------------
extern "C" void kernel_launch(void* const* d_in, const int* in_sizes, int n_in,
                              void* d_out, int out_size)
{
    const float* x  = (const float*)d_in[0];
    const float* Wq = (const float*)d_in[2];
    const float* bq = (const float*)d_in[3];
    const float* Wk = (const float*)d_in[4];
    const float* bk = (const float*)d_in[5];
    const float* Wv = (const float*)d_in[6];
    const float* bv = (const float*)d_in[7];
    const float* Wp = (const float*)d_in[8];
    const float* bp = (const float*)d_in[9];
    float* out = (float*)d_out;

    __half *xe, *we, *qe, *ke, *ve;
    cudaGetSymbolAddress((void**)&xe, g_xe);
    cudaGetSymbolAddress((void**)&we, g_We);
    cudaGetSymbolAddress((void**)&qe, g_Qe);
    cudaGetSymbolAddress((void**)&ke, g_Ke);
    cudaGetSymbolAddress((void**)&ve, g_Ve);
    __half* wpe = we + (size_t)3 * CC * KEXT;

    cudaFuncSetAttribute(gemm_qkv_kernel,
                         cudaFuncAttributeMaxDynamicSharedMemorySize, GSMEM);
    cudaFuncSetAttribute(gemm_out_kernel,
                         cudaFuncAttributeMaxDynamicSharedMemorySize, GSMEM);
    cudaFuncSetAttribute(attn_mma_kernel,
                         cudaFuncAttributeMaxDynamicSharedMemorySize, AT_SMEM);

    // prep
    convert_a_kernel<<<MM, 256>>>(x, xe);
    dim3 wgrd(CC / 32, CC / 32, 4), wblk(32, 8);
    convert_w4_kernel<<<wgrd, wblk>>>(Wq, Wk, Wv, Wp, we);

    // fused QKV projections (K=1024, hi-only)
    dim3 qgrd(CC / 128, MM / 128, 3);  // (8, 32, 3)
    gemm_qkv_kernel<<<qgrd, 256, GSMEM>>>(xe, we, bq, bk, bv, qe, ke, ve);

    // attention (writes [oh|ol] ext layout into xe)
    dim3 agrd(TT / 128, BB * HH);
    attn_mma_kernel<<<agrd, 128, AT_SMEM>>>(qe, ke, ve, xe);

    // output projection (K=2048)
    dim3 ggrd(CC / 128, MM / 128);  // (8, 32)
    gemm_out_kernel<<<ggrd, 256, GSMEM>>>(xe, wpe, bp, out);
}

// round 15
// speedup vs baseline: 1.3007x; 1.0416x over previous
#include <cuda_runtime.h>
#include <cuda_fp16.h>
#include <cstdint>
#include <math.h>

#define BB 2
#define TT 2048
#define CC 1024
#define HH 16
#define DD 64
#define MM (BB*TT)     // 4096
#define KEXT 2048      // [hi | lo] fp16 extended K (row stride)
#define NIT  32        // KEXT / 64   (final projection)
#define NITQ 16        // 1024 / 64   (QKV projections, hi-only)

// ---------------------------------------------------------------------------
// Scratch (__device__ globals; allocation-free rule)
// ---------------------------------------------------------------------------
__device__ __half g_xe[MM*KEXT];          // x hi (cols 0-1023); attention writes [oh|ol]
__device__ __half g_We[4][CC*KEXT];       // [Wh|Wh] transposed (q,k,v,p)
__device__ __half g_Qe[32*TT*64];         // [bh][t][d] fp16, pre-scaled log2e/8
__device__ __half g_Ke[32*TT*64];         // [bh][t][d] single fp16
__device__ __half g_Ve[32*TT*64];         // [bh][t][d] single fp16

// ---------------------------------------------------------------------------
// PTX helpers (sm_80-era: valid at compute_103)
// ---------------------------------------------------------------------------
__device__ __forceinline__ uint32_t smem_to_u32(const void* p) {
    uint32_t a;
    asm("{ .reg .u64 t; cvta.to.shared.u64 t, %1; cvt.u32.u64 %0, t; }"
        : "=r"(a) : "l"(p));
    return a;
}
__device__ __forceinline__ void cp_async16(uint32_t s, const void* g) {
    asm volatile("cp.async.cg.shared.global [%0], [%1], 16;" :: "r"(s), "l"(g));
}
#define CP_COMMIT() asm volatile("cp.async.commit_group;" ::: "memory")
#define CP_WAIT(n)  asm volatile("cp.async.wait_group %0;" :: "n"(n) : "memory")

__device__ __forceinline__ void ldm_x4(uint32_t addr, uint32_t& r0, uint32_t& r1,
                                       uint32_t& r2, uint32_t& r3) {
    asm volatile("ldmatrix.sync.aligned.m8n8.x4.shared.b16 {%0,%1,%2,%3}, [%4];"
                 : "=r"(r0), "=r"(r1), "=r"(r2), "=r"(r3) : "r"(addr));
}
__device__ __forceinline__ void ldm_x4_t(uint32_t addr, uint32_t& r0, uint32_t& r1,
                                         uint32_t& r2, uint32_t& r3) {
    asm volatile("ldmatrix.sync.aligned.m8n8.x4.trans.shared.b16 {%0,%1,%2,%3}, [%4];"
                 : "=r"(r0), "=r"(r1), "=r"(r2), "=r"(r3) : "r"(addr));
}
__device__ __forceinline__ void mma16816(float* c, const uint32_t* a,
                                         uint32_t b0, uint32_t b1) {
    asm volatile("mma.sync.aligned.m16n8k16.row.col.f32.f16.f16.f32 "
                 "{%0,%1,%2,%3}, {%4,%5,%6,%7}, {%8,%9}, {%0,%1,%2,%3};"
                 : "+f"(c[0]), "+f"(c[1]), "+f"(c[2]), "+f"(c[3])
                 : "r"(a[0]), "r"(a[1]), "r"(a[2]), "r"(a[3]), "r"(b0), "r"(b1));
}
__device__ __forceinline__ float ex2f(float x) {
    float r;
    asm("ex2.approx.ftz.f32 %0, %1;" : "=f"(r) : "f"(x));
    return r;
}
__device__ __forceinline__ void split2h(float v0, float v1, uint32_t& hi, uint32_t& lo) {
    __half2 h = __floats2half2_rn(v0, v1);
    float r0 = v0 - __half2float(__low2half(h));
    float r1 = v1 - __half2float(__high2half(h));
    __half2 l = __floats2half2_rn(r0, r1);
    hi = *(uint32_t*)&h; lo = *(uint32_t*)&l;
}
__device__ __forceinline__ uint32_t pack_h2(float v0, float v1) {
    __half2 h = __floats2half2_rn(v0, v1);
    return *(uint32_t*)&h;
}

// ---------------------------------------------------------------------------
// Prep: fp32 [M,1024] -> fp16 hi into xe cols 0-1023 (rows stride 2048)
// ---------------------------------------------------------------------------
__global__ void convert_a_kernel(const float* __restrict__ X,
                                 __half* __restrict__ Xe)
{
    int idx = blockIdx.x * 256 + threadIdx.x;
    int m  = idx >> 8;
    int c4 = (idx & 255) * 4;
    float4 v = *(const float4*)&X[(size_t)m * CC + c4];
    uint32_t h01 = pack_h2(v.x, v.y);
    uint32_t h23 = pack_h2(v.z, v.w);
    *(uint2*)&Xe[(size_t)m * KEXT + c4] = make_uint2(h01, h23);
}

// ---------------------------------------------------------------------------
// Prep (fused x4): W[K,N] fp32 -> We[N,2048] fp16 = [Wh | Wh] (transposed)
// ---------------------------------------------------------------------------
__global__ void convert_w4_kernel(const float* __restrict__ W0,
                                  const float* __restrict__ W1,
                                  const float* __restrict__ W2,
                                  const float* __restrict__ W3,
                                  __half* __restrict__ We)
{
    __shared__ float tile[32][33];
    const float* W = (blockIdx.z == 0) ? W0 : (blockIdx.z == 1) ? W1
                   : (blockIdx.z == 2) ? W2 : W3;
    __half* dst = We + (size_t)blockIdx.z * CC * KEXT;
    int n0 = blockIdx.x * 32, k0 = blockIdx.y * 32;
    int tx = threadIdx.x, ty = threadIdx.y;
#pragma unroll
    for (int r = 0; r < 4; r++)
        tile[ty + 8*r][tx] = W[(size_t)(k0 + ty + 8*r) * CC + n0 + tx];
    __syncthreads();
#pragma unroll
    for (int r = 0; r < 4; r++) {
        int n = n0 + ty + 8*r;
        int k = k0 + tx;
        __half h = __float2half(tile[tx][ty + 8*r]);
        size_t base = (size_t)n * KEXT;
        dst[base + k]        = h;
        dst[base + 1024 + k] = h;
    }
}

// ---------------------------------------------------------------------------
// GEMM machinery: 128x128 tile, K-chunk 64, 3-stage cp.async pipeline.
// ---------------------------------------------------------------------------
#define GROWB 144                        // smem row bytes (64 fp16 + 8 pad)
#define TILE_BYTES (128 * GROWB)         // 18432 per operand
#define GBUF (2 * TILE_BYTES)            // 36864 per stage
#define GSMEM (3 * GBUF)                 // 110592

struct GemmCtx {
    uint32_t sbase;
    int tid, wid, lane, wm, wn;
    uint32_t a_row, a_col, b_row, b_col;
};
__device__ __forceinline__ void gemm_init(GemmCtx& g, uint32_t sbase) {
    g.tid = threadIdx.x; g.wid = g.tid >> 5; g.lane = g.tid & 31;
    g.sbase = sbase;
    g.wm = (g.wid >> 1) * 32; g.wn = (g.wid & 1) * 64;
    g.a_row = g.wm + (g.lane & 15);
    g.a_col = (g.lane >> 4) * 8;
    g.b_row = g.wn + (g.lane & 7) + ((g.lane >> 4) << 3);
    g.b_col = ((g.lane >> 3) & 1) * 8;
}
__device__ __forceinline__ void gemm_issue(const GemmCtx& g, int it,
                                           const __half* A, const __half* B,
                                           int m0, int n0) {
    const int kc = it * 64;
    const uint32_t buf = g.sbase + (it % 3) * GBUF;
#pragma unroll
    for (int i = 0; i < 4; i++) {
        int idx = g.tid + 256 * i;          // 0..1023
        int row = idx >> 3, c = idx & 7;    // 128 rows x 8 chunks
        cp_async16(buf + row * GROWB + c * 16,
                   A + (size_t)(m0 + row) * KEXT + kc + c * 8);
        cp_async16(buf + TILE_BYTES + row * GROWB + c * 16,
                   B + (size_t)(n0 + row) * KEXT + kc + c * 8);
    }
    CP_COMMIT();
}
__device__ __forceinline__ void gemm_step(const GemmCtx& g, int it, float acc[2][8][4]) {
    const uint32_t buf = g.sbase + (it % 3) * GBUF;
    const uint32_t bufB = buf + TILE_BYTES;
#pragma unroll
    for (int ki = 0; ki < 4; ki++) {
        uint32_t a[2][4];
#pragma unroll
        for (int mi = 0; mi < 2; mi++) {
            uint32_t addr = buf + (g.a_row + mi*16) * GROWB + (ki*16 + g.a_col) * 2;
            ldm_x4(addr, a[mi][0], a[mi][1], a[mi][2], a[mi][3]);
        }
        uint32_t b[8][2];
#pragma unroll
        for (int nj = 0; nj < 4; nj++) {
            uint32_t addr = bufB + (g.b_row + nj*16) * GROWB + (ki*16 + g.b_col) * 2;
            uint32_t r0, r1, r2, r3;
            ldm_x4(addr, r0, r1, r2, r3);
            b[2*nj  ][0] = r0; b[2*nj  ][1] = r1;
            b[2*nj+1][0] = r2; b[2*nj+1][1] = r3;
        }
#pragma unroll
        for (int mi = 0; mi < 2; mi++)
#pragma unroll
            for (int nj = 0; nj < 8; nj++)
                mma16816(acc[mi][nj], a[mi], b[nj][0], b[nj][1]);
    }
}

// ---------------------------------------------------------------------------
// Fused QKV projection: K=1024 (hi-only A, Wh half of We).
// ---------------------------------------------------------------------------
__global__ __launch_bounds__(256)
void gemm_qkv_kernel(const __half* __restrict__ Ae,
                     const __half* __restrict__ We,
                     const float* __restrict__ bq,
                     const float* __restrict__ bk,
                     const float* __restrict__ bv,
                     __half* __restrict__ qe,
                     __half* __restrict__ ke,
                     __half* __restrict__ ve)
{
    extern __shared__ __align__(16) char smem[];
    const int z = blockIdx.z;
    const __half* Be = We + (size_t)z * CC * KEXT;
    const float* bias = (z == 0) ? bq : (z == 1) ? bk : bv;
    __half* out = (z == 0) ? qe : (z == 1) ? ke : ve;
    // q pre-scaled by log2(e)/8 so attention can use ex2 directly
    const float escale = (z == 0) ? 0.125f * 1.44269504f : 1.0f;
    const int m0 = blockIdx.y * 128, n0 = blockIdx.x * 128;

    GemmCtx g; gemm_init(g, smem_to_u32(smem));
    float acc[2][8][4];
#pragma unroll
    for (int i = 0; i < 2; i++)
#pragma unroll
        for (int j = 0; j < 8; j++)
#pragma unroll
            for (int k = 0; k < 4; k++) acc[i][j][k] = 0.f;

    gemm_issue(g, 0, Ae, Be, m0, n0);
    gemm_issue(g, 1, Ae, Be, m0, n0);
    for (int it = 0; it < NITQ; it++) {
        CP_WAIT(1);
        __syncthreads();
        if (it + 2 < NITQ) gemm_issue(g, it + 2, Ae, Be, m0, n0); else CP_COMMIT();
        gemm_step(g, it, acc);
    }

    const int erow = m0 + g.wm + (g.lane >> 2);
    const int ecol0 = n0 + g.wn + 2 * (g.lane & 3);
#pragma unroll
    for (int mi = 0; mi < 2; mi++)
#pragma unroll
        for (int nj = 0; nj < 8; nj++) {
            int col = ecol0 + nj * 8;
            float bx = bias[col], by = bias[col + 1];
            int r0 = erow + mi * 16;
            int b_ = r0 >> 11, t = r0 & 2047;
            int h  = col >> 6, d = col & 63;
            __half* base = out + ((size_t)((b_ << 4) + h) * TT + t) * 64 + d;
            *(uint32_t*)base =
                pack_h2((acc[mi][nj][0] + bx) * escale, (acc[mi][nj][1] + by) * escale);
            *(uint32_t*)(base + 512) =
                pack_h2((acc[mi][nj][2] + bx) * escale, (acc[mi][nj][3] + by) * escale);
        }
}

// ---------------------------------------------------------------------------
// Output projection: K=2048 ([oh|ol] ext A), fp32 out.
// ---------------------------------------------------------------------------
__global__ __launch_bounds__(256)
void gemm_out_kernel(const __half* __restrict__ Ae,
                     const __half* __restrict__ Be,
                     const float* __restrict__ bias,
                     float* __restrict__ Cout)
{
    extern __shared__ __align__(16) char smem[];
    const int m0 = blockIdx.y * 128, n0 = blockIdx.x * 128;

    GemmCtx g; gemm_init(g, smem_to_u32(smem));
    float acc[2][8][4];
#pragma unroll
    for (int i = 0; i < 2; i++)
#pragma unroll
        for (int j = 0; j < 8; j++)
#pragma unroll
            for (int k = 0; k < 4; k++) acc[i][j][k] = 0.f;

    gemm_issue(g, 0, Ae, Be, m0, n0);
    gemm_issue(g, 1, Ae, Be, m0, n0);
    for (int it = 0; it < NIT; it++) {
        CP_WAIT(1);
        __syncthreads();
        if (it + 2 < NIT) gemm_issue(g, it + 2, Ae, Be, m0, n0); else CP_COMMIT();
        gemm_step(g, it, acc);
    }

    const int erow = m0 + g.wm + (g.lane >> 2);
    const int ecol0 = n0 + g.wn + 2 * (g.lane & 3);
#pragma unroll
    for (int mi = 0; mi < 2; mi++)
#pragma unroll
        for (int nj = 0; nj < 8; nj++) {
            int col = ecol0 + nj * 8;
            float bx = bias[col], by = bias[col + 1];
            int r0 = erow + mi * 16;
            *(float2*)&Cout[(size_t)r0 * CC + col] =
                make_float2(acc[mi][nj][0] + bx, acc[mi][nj][1] + by);
            *(float2*)&Cout[(size_t)(r0 + 8) * CC + col] =
                make_float2(acc[mi][nj][2] + bx, acc[mi][nj][3] + by);
        }
}

// ---------------------------------------------------------------------------
// MMA flash attention: 64-row Q tile, 4 warps x 16 query rows, wide-S.
// aq held in registers; Q staged once; finer wave quantization (1024 CTAs).
// grid (T/64, B*H), 128 threads, 3 CTA/SM.
// ---------------------------------------------------------------------------
#define KSTR2 144                 // Q/K/V smem row stride bytes (64 fp16 + pad)
#define ATQ_SZ (64 * KSTR2)       // 9216 (persistent Q tile, 64 rows)
#define AT_VOFF (64 * KSTR2)      // 9216
#define AT_BUF  (2 * 64 * KSTR2)  // 18432 per KV buffer
#define AT_SMEM (ATQ_SZ + 2 * AT_BUF)  // 46080 (dynamic)

__global__ __launch_bounds__(128, 3)
void attn_mma_kernel(const __half* __restrict__ Qe,
                     const __half* __restrict__ Ke,
                     const __half* __restrict__ Ve,
                     __half* __restrict__ oe)
{
    extern __shared__ __align__(16) char smem[];
    const uint32_t sbase = smem_to_u32(smem);
    const uint32_t kvbase = sbase + ATQ_SZ;
    const int tid  = threadIdx.x;
    const int wid  = tid >> 5;
    const int lane = tid & 31;
    const int qb   = blockIdx.x;
    const int bh   = blockIdx.y;
    const int wm   = wid * 16;          // 16 query rows per warp

    const __half* Qg = Qe + ((size_t)bh * TT + qb * 64) * 64;
    const __half* Kg = Ke + (size_t)bh * TT * 64;
    const __half* Vg = Ve + (size_t)bh * TT * 64;

    // --- stage Q tile (64 rows x 8 chunks = 512) ---
#pragma unroll
    for (int i = 0; i < 4; i++) {
        int idx = tid + 128 * i;           // 0..511
        int row = idx >> 3, c = idx & 7;
        cp_async16(sbase + row * KSTR2 + c * 16, Qg + (size_t)row * 64 + c * 8);
    }
    CP_COMMIT();

    auto issue = [&](int kt) {
        const uint32_t buf = kvbase + (kt & 1) * AT_BUF;
        const int r0 = kt * 64;
#pragma unroll
        for (int i = 0; i < 4; i++) {
            int idx = tid + 128 * i;       // 0..511 (64 rows x 8 chunks)
            int row = idx >> 3, c = idx & 7;
            cp_async16(buf + row * KSTR2 + c * 16, Kg + (size_t)(r0 + row) * 64 + c * 8);
            cp_async16(buf + AT_VOFF + row * KSTR2 + c * 16, Vg + (size_t)(r0 + row) * 64 + c * 8);
        }
        CP_COMMIT();
    };

    issue(0);           // pending: {Q, KV0}
    CP_WAIT(1);         // Q done
    __syncthreads();

    // --- load persistent Q frags (held all kernel: 16 regs) ---
    uint32_t aq[4][4];
    {
        const uint32_t qfrag = sbase + (wm + (lane & 15)) * KSTR2 + ((lane >> 4) * 8) * 2;
#pragma unroll
        for (int c = 0; c < 4; c++)
            ldm_x4(qfrag + c * 32, aq[c][0], aq[c][1], aq[c][2], aq[c][3]);
    }

    float oacc[8][4];
#pragma unroll
    for (int j = 0; j < 8; j++)
#pragma unroll
        for (int k = 0; k < 4; k++) oacc[j][k] = 0.f;
    float lsum0 = 0.f, lsum1 = 0.f;

    const uint32_t frow_off = ((lane & 7) + ((lane >> 3) & 1) * 8) * KSTR2;
    const uint32_t fcol_off = ((lane >> 4) * 8) * 2;

    for (int it = 0; it < TT / 64; it++) {
        if (it + 1 < TT / 64) { issue(it + 1); CP_WAIT(1); }
        else                  { CP_WAIT(0); }
        __syncthreads();
        const uint32_t kb = kvbase + (it & 1) * AT_BUF + frow_off + fcol_off;
        const uint32_t vb = kb + AT_VOFF;

        // ---- S = q . k^T (wide) ----
        float s[8][4];
#pragma unroll
        for (int j = 0; j < 8; j++)
#pragma unroll
            for (int k = 0; k < 4; k++) s[j][k] = 0.f;

#pragma unroll
        for (int g = 0; g < 4; g++) {
            uint32_t grow = kb + g * (16 * KSTR2);
#pragma unroll
            for (int c = 0; c < 4; c++) {
                uint32_t r0, r1, r2, r3;
                ldm_x4(grow + c * 32, r0, r1, r2, r3);
                mma16816(s[2*g],   aq[c], r0, r2);
                mma16816(s[2*g+1], aq[c], r1, r3);
            }
        }

        // ---- P = ex2(S), pack fp16 ----
        uint32_t ph[4][4];
#pragma unroll
        for (int g = 0; g < 4; g++) {
            float e0 = ex2f(s[2*g][0]),   e1 = ex2f(s[2*g][1]);
            float e2 = ex2f(s[2*g][2]),   e3 = ex2f(s[2*g][3]);
            float e4 = ex2f(s[2*g+1][0]), e5 = ex2f(s[2*g+1][1]);
            float e6 = ex2f(s[2*g+1][2]), e7 = ex2f(s[2*g+1][3]);
            lsum0 += e0 + e1 + e4 + e5;
            lsum1 += e2 + e3 + e6 + e7;
            ph[g][0] = pack_h2(e0, e1);
            ph[g][1] = pack_h2(e2, e3);
            ph[g][2] = pack_h2(e4, e5);
            ph[g][3] = pack_h2(e6, e7);
        }

        // ---- O += p . v ----
#pragma unroll
        for (int g = 0; g < 4; g++) {
            uint32_t vrb = vb + g * (16 * KSTR2);
#pragma unroll
            for (int ng = 0; ng < 4; ng++) {
                uint32_t r0, r1, r2, r3;
                ldm_x4_t(vrb + ng * 32, r0, r1, r2, r3);
                mma16816(oacc[2*ng],   ph[g], r0, r1);
                mma16816(oacc[2*ng+1], ph[g], r2, r3);
            }
        }
        __syncthreads();
    }

    // ---- normalize + write [oh | ol] ext rows into oe [M, 2048] ----
    lsum0 += __shfl_xor_sync(0xFFFFFFFF, lsum0, 1);
    lsum0 += __shfl_xor_sync(0xFFFFFFFF, lsum0, 2);
    lsum1 += __shfl_xor_sync(0xFFFFFFFF, lsum1, 1);
    lsum1 += __shfl_xor_sync(0xFFFFFFFF, lsum1, 2);
    float inv0 = 1.f / lsum0, inv1 = 1.f / lsum1;

    int b_ = bh >> 4, h = bh & 15;
    int t0 = qb * 64 + wm + (lane >> 2);
    size_t m = (size_t)b_ * TT + t0;
    int colb = h * 64 + 2 * (lane & 3);
#pragma unroll
    for (int nj = 0; nj < 8; nj++) {
        int col = colb + nj * 8;
        uint32_t hi, lo;
        __half* base = oe + m * KEXT + col;
        split2h(oacc[nj][0] * inv0, oacc[nj][1] * inv0, hi, lo);
        *(uint32_t*)base = hi; *(uint32_t*)(base + 1024) = lo;
        base += (size_t)8 * KEXT;
        split2h(oacc[nj][2] * inv1, oacc[nj][3] * inv1, hi, lo);
        *(uint32_t*)base = hi; *(uint32_t*)(base + 1024) = lo;
    }
}

// ---------------------------------------------------------------------------
extern "C" void kernel_launch(void* const* d_in, const int* in_sizes, int n_in,
                              void* d_out, int out_size)
{
    const float* x  = (const float*)d_in[0];
    const float* Wq = (const float*)d_in[2];
    const float* bq = (const float*)d_in[3];
    const float* Wk = (const float*)d_in[4];
    const float* bk = (const float*)d_in[5];
    const float* Wv = (const float*)d_in[6];
    const float* bv = (const float*)d_in[7];
    const float* Wp = (const float*)d_in[8];
    const float* bp = (const float*)d_in[9];
    float* out = (float*)d_out;

    __half *xe, *we, *qe, *ke, *ve;
    cudaGetSymbolAddress((void**)&xe, g_xe);
    cudaGetSymbolAddress((void**)&we, g_We);
    cudaGetSymbolAddress((void**)&qe, g_Qe);
    cudaGetSymbolAddress((void**)&ke, g_Ke);
    cudaGetSymbolAddress((void**)&ve, g_Ve);
    __half* wpe = we + (size_t)3 * CC * KEXT;

    cudaFuncSetAttribute(gemm_qkv_kernel,
                         cudaFuncAttributeMaxDynamicSharedMemorySize, GSMEM);
    cudaFuncSetAttribute(gemm_out_kernel,
                         cudaFuncAttributeMaxDynamicSharedMemorySize, GSMEM);
    cudaFuncSetAttribute(attn_mma_kernel,
                         cudaFuncAttributeMaxDynamicSharedMemorySize, AT_SMEM);

    // prep
    convert_a_kernel<<<MM, 256>>>(x, xe);
    dim3 wgrd(CC / 32, CC / 32, 4), wblk(32, 8);
    convert_w4_kernel<<<wgrd, wblk>>>(Wq, Wk, Wv, Wp, we);

    // fused QKV projections (K=1024, hi-only)
    dim3 qgrd(CC / 128, MM / 128, 3);  // (8, 32, 3)
    gemm_qkv_kernel<<<qgrd, 256, GSMEM>>>(xe, we, bq, bk, bv, qe, ke, ve);

    // attention (writes [oh|ol] ext layout into xe)
    dim3 agrd(TT / 64, BB * HH);       // (32, 32) = 1024 CTAs
    attn_mma_kernel<<<agrd, 128, AT_SMEM>>>(qe, ke, ve, xe);

    // output projection (K=2048)
    dim3 ggrd(CC / 128, MM / 128);  // (8, 32)
    gemm_out_kernel<<<ggrd, 256, GSMEM>>>(xe, wpe, bp, out);
}

// round 16
// speedup vs baseline: 1.4864x; 1.1428x over previous
#include <cuda_runtime.h>
#include <cuda_fp16.h>
#include <cstdint>
#include <math.h>

#define BB 2
#define TT 2048
#define CC 1024
#define HH 16
#define DD 64
#define MM (BB*TT)     // 4096
#define KEXT 2048      // fp16 extended row stride
#define NIT  16        // 1024 / 64   (output projection, hi-only now)
#define NITQ 16        // 1024 / 64   (QKV projections, hi-only)

// ---------------------------------------------------------------------------
// Scratch (__device__ globals; allocation-free rule)
// ---------------------------------------------------------------------------
__device__ __half g_xe[MM*KEXT];          // x hi (cols 0-1023); attention writes oh
__device__ __half g_We[4][CC*KEXT];       // [Wh|Wh] transposed (q,k,v,p)
__device__ __half g_Qe[32*TT*64];         // [bh][t][d] fp16, pre-scaled log2e/8
__device__ __half g_Ke[32*TT*64];         // [bh][t][d] single fp16
__device__ __half g_Ve[32*TT*64];         // [bh][t][d] single fp16

// ---------------------------------------------------------------------------
// PTX helpers (sm_80-era: valid at compute_103)
// ---------------------------------------------------------------------------
__device__ __forceinline__ uint32_t smem_to_u32(const void* p) {
    uint32_t a;
    asm("{ .reg .u64 t; cvta.to.shared.u64 t, %1; cvt.u32.u64 %0, t; }"
        : "=r"(a) : "l"(p));
    return a;
}
__device__ __forceinline__ void cp_async16(uint32_t s, const void* g) {
    asm volatile("cp.async.cg.shared.global [%0], [%1], 16;" :: "r"(s), "l"(g));
}
#define CP_COMMIT() asm volatile("cp.async.commit_group;" ::: "memory")
#define CP_WAIT(n)  asm volatile("cp.async.wait_group %0;" :: "n"(n) : "memory")

__device__ __forceinline__ void ldm_x4(uint32_t addr, uint32_t& r0, uint32_t& r1,
                                       uint32_t& r2, uint32_t& r3) {
    asm volatile("ldmatrix.sync.aligned.m8n8.x4.shared.b16 {%0,%1,%2,%3}, [%4];"
                 : "=r"(r0), "=r"(r1), "=r"(r2), "=r"(r3) : "r"(addr));
}
__device__ __forceinline__ void ldm_x4_t(uint32_t addr, uint32_t& r0, uint32_t& r1,
                                         uint32_t& r2, uint32_t& r3) {
    asm volatile("ldmatrix.sync.aligned.m8n8.x4.trans.shared.b16 {%0,%1,%2,%3}, [%4];"
                 : "=r"(r0), "=r"(r1), "=r"(r2), "=r"(r3) : "r"(addr));
}
__device__ __forceinline__ void mma16816(float* c, const uint32_t* a,
                                         uint32_t b0, uint32_t b1) {
    asm volatile("mma.sync.aligned.m16n8k16.row.col.f32.f16.f16.f32 "
                 "{%0,%1,%2,%3}, {%4,%5,%6,%7}, {%8,%9}, {%0,%1,%2,%3};"
                 : "+f"(c[0]), "+f"(c[1]), "+f"(c[2]), "+f"(c[3])
                 : "r"(a[0]), "r"(a[1]), "r"(a[2]), "r"(a[3]), "r"(b0), "r"(b1));
}
__device__ __forceinline__ float ex2f(float x) {
    float r;
    asm("ex2.approx.ftz.f32 %0, %1;" : "=f"(r) : "f"(x));
    return r;
}
__device__ __forceinline__ uint32_t pack_h2(float v0, float v1) {
    __half2 h = __floats2half2_rn(v0, v1);
    return *(uint32_t*)&h;
}

// ---------------------------------------------------------------------------
// Prep: fp32 [M,1024] -> fp16 hi into xe cols 0-1023 (rows stride 2048)
// ---------------------------------------------------------------------------
__global__ void convert_a_kernel(const float* __restrict__ X,
                                 __half* __restrict__ Xe)
{
    int idx = blockIdx.x * 256 + threadIdx.x;
    int m  = idx >> 8;
    int c4 = (idx & 255) * 4;
    float4 v = *(const float4*)&X[(size_t)m * CC + c4];
    uint32_t h01 = pack_h2(v.x, v.y);
    uint32_t h23 = pack_h2(v.z, v.w);
    *(uint2*)&Xe[(size_t)m * KEXT + c4] = make_uint2(h01, h23);
}

// ---------------------------------------------------------------------------
// Prep (fused x4): W[K,N] fp32 -> We[N,2048] fp16 = [Wh | Wh] (transposed)
// ---------------------------------------------------------------------------
__global__ void convert_w4_kernel(const float* __restrict__ W0,
                                  const float* __restrict__ W1,
                                  const float* __restrict__ W2,
                                  const float* __restrict__ W3,
                                  __half* __restrict__ We)
{
    __shared__ float tile[32][33];
    const float* W = (blockIdx.z == 0) ? W0 : (blockIdx.z == 1) ? W1
                   : (blockIdx.z == 2) ? W2 : W3;
    __half* dst = We + (size_t)blockIdx.z * CC * KEXT;
    int n0 = blockIdx.x * 32, k0 = blockIdx.y * 32;
    int tx = threadIdx.x, ty = threadIdx.y;
#pragma unroll
    for (int r = 0; r < 4; r++)
        tile[ty + 8*r][tx] = W[(size_t)(k0 + ty + 8*r) * CC + n0 + tx];
    __syncthreads();
#pragma unroll
    for (int r = 0; r < 4; r++) {
        int n = n0 + ty + 8*r;
        int k = k0 + tx;
        __half h = __float2half(tile[tx][ty + 8*r]);
        size_t base = (size_t)n * KEXT;
        dst[base + k]        = h;
        dst[base + 1024 + k] = h;
    }
}

// ---------------------------------------------------------------------------
// GEMM machinery: 128x128 tile, K-chunk 64, 3-stage cp.async pipeline.
// ---------------------------------------------------------------------------
#define GROWB 144                        // smem row bytes (64 fp16 + 8 pad)
#define TILE_BYTES (128 * GROWB)         // 18432 per operand
#define GBUF (2 * TILE_BYTES)            // 36864 per stage
#define GSMEM (3 * GBUF)                 // 110592

struct GemmCtx {
    uint32_t sbase;
    int tid, wid, lane, wm, wn;
    uint32_t a_row, a_col, b_row, b_col;
};
__device__ __forceinline__ void gemm_init(GemmCtx& g, uint32_t sbase) {
    g.tid = threadIdx.x; g.wid = g.tid >> 5; g.lane = g.tid & 31;
    g.sbase = sbase;
    g.wm = (g.wid >> 1) * 32; g.wn = (g.wid & 1) * 64;
    g.a_row = g.wm + (g.lane & 15);
    g.a_col = (g.lane >> 4) * 8;
    g.b_row = g.wn + (g.lane & 7) + ((g.lane >> 4) << 3);
    g.b_col = ((g.lane >> 3) & 1) * 8;
}
__device__ __forceinline__ void gemm_issue(const GemmCtx& g, int it,
                                           const __half* A, const __half* B,
                                           int m0, int n0) {
    const int kc = it * 64;
    const uint32_t buf = g.sbase + (it % 3) * GBUF;
#pragma unroll
    for (int i = 0; i < 4; i++) {
        int idx = g.tid + 256 * i;          // 0..1023
        int row = idx >> 3, c = idx & 7;    // 128 rows x 8 chunks
        cp_async16(buf + row * GROWB + c * 16,
                   A + (size_t)(m0 + row) * KEXT + kc + c * 8);
        cp_async16(buf + TILE_BYTES + row * GROWB + c * 16,
                   B + (size_t)(n0 + row) * KEXT + kc + c * 8);
    }
    CP_COMMIT();
}
__device__ __forceinline__ void gemm_step(const GemmCtx& g, int it, float acc[2][8][4]) {
    const uint32_t buf = g.sbase + (it % 3) * GBUF;
    const uint32_t bufB = buf + TILE_BYTES;
#pragma unroll
    for (int ki = 0; ki < 4; ki++) {
        uint32_t a[2][4];
#pragma unroll
        for (int mi = 0; mi < 2; mi++) {
            uint32_t addr = buf + (g.a_row + mi*16) * GROWB + (ki*16 + g.a_col) * 2;
            ldm_x4(addr, a[mi][0], a[mi][1], a[mi][2], a[mi][3]);
        }
        uint32_t b[8][2];
#pragma unroll
        for (int nj = 0; nj < 4; nj++) {
            uint32_t addr = bufB + (g.b_row + nj*16) * GROWB + (ki*16 + g.b_col) * 2;
            uint32_t r0, r1, r2, r3;
            ldm_x4(addr, r0, r1, r2, r3);
            b[2*nj  ][0] = r0; b[2*nj  ][1] = r1;
            b[2*nj+1][0] = r2; b[2*nj+1][1] = r3;
        }
#pragma unroll
        for (int mi = 0; mi < 2; mi++)
#pragma unroll
            for (int nj = 0; nj < 8; nj++)
                mma16816(acc[mi][nj], a[mi], b[nj][0], b[nj][1]);
    }
}

// ---------------------------------------------------------------------------
// Fused QKV projection: K=1024 (hi-only A, Wh half of We).
// ---------------------------------------------------------------------------
__global__ __launch_bounds__(256)
void gemm_qkv_kernel(const __half* __restrict__ Ae,
                     const __half* __restrict__ We,
                     const float* __restrict__ bq,
                     const float* __restrict__ bk,
                     const float* __restrict__ bv,
                     __half* __restrict__ qe,
                     __half* __restrict__ ke,
                     __half* __restrict__ ve)
{
    extern __shared__ __align__(16) char smem[];
    const int z = blockIdx.z;
    const __half* Be = We + (size_t)z * CC * KEXT;
    const float* bias = (z == 0) ? bq : (z == 1) ? bk : bv;
    __half* out = (z == 0) ? qe : (z == 1) ? ke : ve;
    // q pre-scaled by log2(e)/8 so attention can use ex2 directly
    const float escale = (z == 0) ? 0.125f * 1.44269504f : 1.0f;
    const int m0 = blockIdx.y * 128, n0 = blockIdx.x * 128;

    GemmCtx g; gemm_init(g, smem_to_u32(smem));
    float acc[2][8][4];
#pragma unroll
    for (int i = 0; i < 2; i++)
#pragma unroll
        for (int j = 0; j < 8; j++)
#pragma unroll
            for (int k = 0; k < 4; k++) acc[i][j][k] = 0.f;

    gemm_issue(g, 0, Ae, Be, m0, n0);
    gemm_issue(g, 1, Ae, Be, m0, n0);
    for (int it = 0; it < NITQ; it++) {
        CP_WAIT(1);
        __syncthreads();
        if (it + 2 < NITQ) gemm_issue(g, it + 2, Ae, Be, m0, n0); else CP_COMMIT();
        gemm_step(g, it, acc);
    }

    const int erow = m0 + g.wm + (g.lane >> 2);
    const int ecol0 = n0 + g.wn + 2 * (g.lane & 3);
#pragma unroll
    for (int mi = 0; mi < 2; mi++)
#pragma unroll
        for (int nj = 0; nj < 8; nj++) {
            int col = ecol0 + nj * 8;
            float bx = bias[col], by = bias[col + 1];
            int r0 = erow + mi * 16;
            int b_ = r0 >> 11, t = r0 & 2047;
            int h  = col >> 6, d = col & 63;
            __half* base = out + ((size_t)((b_ << 4) + h) * TT + t) * 64 + d;
            *(uint32_t*)base =
                pack_h2((acc[mi][nj][0] + bx) * escale, (acc[mi][nj][1] + by) * escale);
            *(uint32_t*)(base + 512) =
                pack_h2((acc[mi][nj][2] + bx) * escale, (acc[mi][nj][3] + by) * escale);
        }
}

// ---------------------------------------------------------------------------
// Output projection: K=1024 (oh only), fp32 out.
// ---------------------------------------------------------------------------
__global__ __launch_bounds__(256)
void gemm_out_kernel(const __half* __restrict__ Ae,
                     const __half* __restrict__ Be,
                     const float* __restrict__ bias,
                     float* __restrict__ Cout)
{
    extern __shared__ __align__(16) char smem[];
    const int m0 = blockIdx.y * 128, n0 = blockIdx.x * 128;

    GemmCtx g; gemm_init(g, smem_to_u32(smem));
    float acc[2][8][4];
#pragma unroll
    for (int i = 0; i < 2; i++)
#pragma unroll
        for (int j = 0; j < 8; j++)
#pragma unroll
            for (int k = 0; k < 4; k++) acc[i][j][k] = 0.f;

    gemm_issue(g, 0, Ae, Be, m0, n0);
    gemm_issue(g, 1, Ae, Be, m0, n0);
    for (int it = 0; it < NIT; it++) {
        CP_WAIT(1);
        __syncthreads();
        if (it + 2 < NIT) gemm_issue(g, it + 2, Ae, Be, m0, n0); else CP_COMMIT();
        gemm_step(g, it, acc);
    }

    const int erow = m0 + g.wm + (g.lane >> 2);
    const int ecol0 = n0 + g.wn + 2 * (g.lane & 3);
#pragma unroll
    for (int mi = 0; mi < 2; mi++)
#pragma unroll
        for (int nj = 0; nj < 8; nj++) {
            int col = ecol0 + nj * 8;
            float bx = bias[col], by = bias[col + 1];
            int r0 = erow + mi * 16;
            *(float2*)&Cout[(size_t)r0 * CC + col] =
                make_float2(acc[mi][nj][0] + bx, acc[mi][nj][1] + by);
            *(float2*)&Cout[(size_t)(r0 + 8) * CC + col] =
                make_float2(acc[mi][nj][2] + bx, acc[mi][nj][3] + by);
        }
}

// ---------------------------------------------------------------------------
// MMA flash attention: 64-row Q tile, 4 warps x 16 query rows, wide-S.
// aq persistent in regs; forced 4 CTA/SM (592 slots, 1024 CTAs = 1.73 waves).
// grid (T/64, B*H), 128 threads.
// ---------------------------------------------------------------------------
#define KSTR2 144                 // Q/K/V smem row stride bytes (64 fp16 + pad)
#define ATQ_SZ (64 * KSTR2)       // 9216 (persistent Q tile, 64 rows)
#define AT_VOFF (64 * KSTR2)      // 9216
#define AT_BUF  (2 * 64 * KSTR2)  // 18432 per KV buffer
#define AT_SMEM (ATQ_SZ + 2 * AT_BUF)  // 46080 (dynamic)

__global__ __launch_bounds__(128, 4)
void attn_mma_kernel(const __half* __restrict__ Qe,
                     const __half* __restrict__ Ke,
                     const __half* __restrict__ Ve,
                     __half* __restrict__ oe)
{
    extern __shared__ __align__(16) char smem[];
    const uint32_t sbase = smem_to_u32(smem);
    const uint32_t kvbase = sbase + ATQ_SZ;
    const int tid  = threadIdx.x;
    const int wid  = tid >> 5;
    const int lane = tid & 31;
    const int qb   = blockIdx.x;
    const int bh   = blockIdx.y;
    const int wm   = wid * 16;          // 16 query rows per warp

    const __half* Qg = Qe + ((size_t)bh * TT + qb * 64) * 64;
    const __half* Kg = Ke + (size_t)bh * TT * 64;
    const __half* Vg = Ve + (size_t)bh * TT * 64;

    // --- stage Q tile (64 rows x 8 chunks = 512) ---
#pragma unroll
    for (int i = 0; i < 4; i++) {
        int idx = tid + 128 * i;           // 0..511
        int row = idx >> 3, c = idx & 7;
        cp_async16(sbase + row * KSTR2 + c * 16, Qg + (size_t)row * 64 + c * 8);
    }
    CP_COMMIT();

    auto issue = [&](int kt) {
        const uint32_t buf = kvbase + (kt & 1) * AT_BUF;
        const int r0 = kt * 64;
#pragma unroll
        for (int i = 0; i < 4; i++) {
            int idx = tid + 128 * i;       // 0..511 (64 rows x 8 chunks)
            int row = idx >> 3, c = idx & 7;
            cp_async16(buf + row * KSTR2 + c * 16, Kg + (size_t)(r0 + row) * 64 + c * 8);
            cp_async16(buf + AT_VOFF + row * KSTR2 + c * 16, Vg + (size_t)(r0 + row) * 64 + c * 8);
        }
        CP_COMMIT();
    };

    issue(0);           // pending: {Q, KV0}
    CP_WAIT(1);         // Q done
    __syncthreads();

    // --- load persistent Q frags (held all kernel: 16 regs) ---
    uint32_t aq[4][4];
    {
        const uint32_t qfrag = sbase + (wm + (lane & 15)) * KSTR2 + ((lane >> 4) * 8) * 2;
#pragma unroll
        for (int c = 0; c < 4; c++)
            ldm_x4(qfrag + c * 32, aq[c][0], aq[c][1], aq[c][2], aq[c][3]);
    }

    float oacc[8][4];
#pragma unroll
    for (int j = 0; j < 8; j++)
#pragma unroll
        for (int k = 0; k < 4; k++) oacc[j][k] = 0.f;
    float lsum0 = 0.f, lsum1 = 0.f;

    const uint32_t frow_off = ((lane & 7) + ((lane >> 3) & 1) * 8) * KSTR2;
    const uint32_t fcol_off = ((lane >> 4) * 8) * 2;

    for (int it = 0; it < TT / 64; it++) {
        if (it + 1 < TT / 64) { issue(it + 1); CP_WAIT(1); }
        else                  { CP_WAIT(0); }
        __syncthreads();
        const uint32_t kb = kvbase + (it & 1) * AT_BUF + frow_off + fcol_off;
        const uint32_t vb = kb + AT_VOFF;

        // ---- S = q . k^T (wide) ----
        float s[8][4];
#pragma unroll
        for (int j = 0; j < 8; j++)
#pragma unroll
            for (int k = 0; k < 4; k++) s[j][k] = 0.f;

#pragma unroll
        for (int g = 0; g < 4; g++) {
            uint32_t grow = kb + g * (16 * KSTR2);
#pragma unroll
            for (int c = 0; c < 4; c++) {
                uint32_t r0, r1, r2, r3;
                ldm_x4(grow + c * 32, r0, r1, r2, r3);
                mma16816(s[2*g],   aq[c], r0, r2);
                mma16816(s[2*g+1], aq[c], r1, r3);
            }
        }

        // ---- P = ex2(S), pack fp16 ----
        uint32_t ph[4][4];
#pragma unroll
        for (int g = 0; g < 4; g++) {
            float e0 = ex2f(s[2*g][0]),   e1 = ex2f(s[2*g][1]);
            float e2 = ex2f(s[2*g][2]),   e3 = ex2f(s[2*g][3]);
            float e4 = ex2f(s[2*g+1][0]), e5 = ex2f(s[2*g+1][1]);
            float e6 = ex2f(s[2*g+1][2]), e7 = ex2f(s[2*g+1][3]);
            lsum0 += e0 + e1 + e4 + e5;
            lsum1 += e2 + e3 + e6 + e7;
            ph[g][0] = pack_h2(e0, e1);
            ph[g][1] = pack_h2(e2, e3);
            ph[g][2] = pack_h2(e4, e5);
            ph[g][3] = pack_h2(e6, e7);
        }

        // ---- O += p . v ----
#pragma unroll
        for (int g = 0; g < 4; g++) {
            uint32_t vrb = vb + g * (16 * KSTR2);
#pragma unroll
            for (int ng = 0; ng < 4; ng++) {
                uint32_t r0, r1, r2, r3;
                ldm_x4_t(vrb + ng * 32, r0, r1, r2, r3);
                mma16816(oacc[2*ng],   ph[g], r0, r1);
                mma16816(oacc[2*ng+1], ph[g], r2, r3);
            }
        }
        __syncthreads();
    }

    // ---- normalize + write oh (single fp16) into oe [M, 2048] cols 0-1023 ----
    lsum0 += __shfl_xor_sync(0xFFFFFFFF, lsum0, 1);
    lsum0 += __shfl_xor_sync(0xFFFFFFFF, lsum0, 2);
    lsum1 += __shfl_xor_sync(0xFFFFFFFF, lsum1, 1);
    lsum1 += __shfl_xor_sync(0xFFFFFFFF, lsum1, 2);
    float inv0 = 1.f / lsum0, inv1 = 1.f / lsum1;

    int b_ = bh >> 4, h = bh & 15;
    int t0 = qb * 64 + wm + (lane >> 2);
    size_t m = (size_t)b_ * TT + t0;
    int colb = h * 64 + 2 * (lane & 3);
#pragma unroll
    for (int nj = 0; nj < 8; nj++) {
        int col = colb + nj * 8;
        __half* base = oe + m * KEXT + col;
        *(uint32_t*)base = pack_h2(oacc[nj][0] * inv0, oacc[nj][1] * inv0);
        *(uint32_t*)(base + 8 * KEXT) = pack_h2(oacc[nj][2] * inv1, oacc[nj][3] * inv1);
    }
}

// ---------------------------------------------------------------------------
extern "C" void kernel_launch(void* const* d_in, const int* in_sizes, int n_in,
                              void* d_out, int out_size)
{
    const float* x  = (const float*)d_in[0];
    const float* Wq = (const float*)d_in[2];
    const float* bq = (const float*)d_in[3];
    const float* Wk = (const float*)d_in[4];
    const float* bk = (const float*)d_in[5];
    const float* Wv = (const float*)d_in[6];
    const float* bv = (const float*)d_in[7];
    const float* Wp = (const float*)d_in[8];
    const float* bp = (const float*)d_in[9];
    float* out = (float*)d_out;

    __half *xe, *we, *qe, *ke, *ve;
    cudaGetSymbolAddress((void**)&xe, g_xe);
    cudaGetSymbolAddress((void**)&we, g_We);
    cudaGetSymbolAddress((void**)&qe, g_Qe);
    cudaGetSymbolAddress((void**)&ke, g_Ke);
    cudaGetSymbolAddress((void**)&ve, g_Ve);
    __half* wpe = we + (size_t)3 * CC * KEXT;

    cudaFuncSetAttribute(gemm_qkv_kernel,
                         cudaFuncAttributeMaxDynamicSharedMemorySize, GSMEM);
    cudaFuncSetAttribute(gemm_out_kernel,
                         cudaFuncAttributeMaxDynamicSharedMemorySize, GSMEM);
    cudaFuncSetAttribute(attn_mma_kernel,
                         cudaFuncAttributeMaxDynamicSharedMemorySize, AT_SMEM);

    // prep
    convert_a_kernel<<<MM, 256>>>(x, xe);
    dim3 wgrd(CC / 32, CC / 32, 4), wblk(32, 8);
    convert_w4_kernel<<<wgrd, wblk>>>(Wq, Wk, Wv, Wp, we);

    // fused QKV projections (K=1024, hi-only)
    dim3 qgrd(CC / 128, MM / 128, 3);  // (8, 32, 3)
    gemm_qkv_kernel<<<qgrd, 256, GSMEM>>>(xe, we, bq, bk, bv, qe, ke, ve);

    // attention (writes oh into xe cols 0-1023)
    dim3 agrd(TT / 64, BB * HH);       // (32, 32) = 1024 CTAs
    attn_mma_kernel<<<agrd, 128, AT_SMEM>>>(qe, ke, ve, xe);

    // output projection (K=1024, oh only)
    dim3 ggrd(CC / 128, MM / 128);  // (8, 32)
    gemm_out_kernel<<<ggrd, 256, GSMEM>>>(xe, wpe, bp, out);
}

// round 17
// speedup vs baseline: 1.5184x; 1.0215x over previous
#include <cuda_runtime.h>
#include <cuda_fp16.h>
#include <cstdint>
#include <math.h>

#define BB 2
#define TT 2048
#define CC 1024
#define HH 16
#define DD 64
#define MM (BB*TT)     // 4096
#define KEXT 2048      // fp16 extended row stride
#define NIT  16        // 1024 / 64   (output projection, hi-only)
#define NITQ 16        // 1024 / 64   (QKV projections, hi-only)

// ---------------------------------------------------------------------------
// Scratch (__device__ globals; allocation-free rule)
// ---------------------------------------------------------------------------
__device__ __half g_xe[MM*KEXT];          // x hi (cols 0-1023); attention writes oh
__device__ __half g_We[4][CC*KEXT];       // [Wh|Wh] transposed (q,k,v,p)
__device__ __half g_Qe[32*TT*64];         // [bh][t][d] fp16, pre-scaled log2e/8
__device__ __half g_Ke[32*TT*64];         // [bh][t][d] single fp16
__device__ __half g_Ve[32*TT*64];         // [bh][t][d] single fp16

// ---------------------------------------------------------------------------
// PTX helpers (sm_80-era: valid at compute_103)
// ---------------------------------------------------------------------------
__device__ __forceinline__ uint32_t smem_to_u32(const void* p) {
    uint32_t a;
    asm("{ .reg .u64 t; cvta.to.shared.u64 t, %1; cvt.u32.u64 %0, t; }"
        : "=r"(a) : "l"(p));
    return a;
}
__device__ __forceinline__ void cp_async16(uint32_t s, const void* g) {
    asm volatile("cp.async.cg.shared.global [%0], [%1], 16;" :: "r"(s), "l"(g));
}
#define CP_COMMIT() asm volatile("cp.async.commit_group;" ::: "memory")
#define CP_WAIT(n)  asm volatile("cp.async.wait_group %0;" :: "n"(n) : "memory")

__device__ __forceinline__ void ldm_x4(uint32_t addr, uint32_t& r0, uint32_t& r1,
                                       uint32_t& r2, uint32_t& r3) {
    asm volatile("ldmatrix.sync.aligned.m8n8.x4.shared.b16 {%0,%1,%2,%3}, [%4];"
                 : "=r"(r0), "=r"(r1), "=r"(r2), "=r"(r3) : "r"(addr));
}
__device__ __forceinline__ void ldm_x4_t(uint32_t addr, uint32_t& r0, uint32_t& r1,
                                         uint32_t& r2, uint32_t& r3) {
    asm volatile("ldmatrix.sync.aligned.m8n8.x4.trans.shared.b16 {%0,%1,%2,%3}, [%4];"
                 : "=r"(r0), "=r"(r1), "=r"(r2), "=r"(r3) : "r"(addr));
}
__device__ __forceinline__ void mma16816(float* c, const uint32_t* a,
                                         uint32_t b0, uint32_t b1) {
    asm volatile("mma.sync.aligned.m16n8k16.row.col.f32.f16.f16.f32 "
                 "{%0,%1,%2,%3}, {%4,%5,%6,%7}, {%8,%9}, {%0,%1,%2,%3};"
                 : "+f"(c[0]), "+f"(c[1]), "+f"(c[2]), "+f"(c[3])
                 : "r"(a[0]), "r"(a[1]), "r"(a[2]), "r"(a[3]), "r"(b0), "r"(b1));
}
__device__ __forceinline__ float ex2f(float x) {
    float r;
    asm("ex2.approx.ftz.f32 %0, %1;" : "=f"(r) : "f"(x));
    return r;
}
__device__ __forceinline__ uint32_t pack_h2(float v0, float v1) {
    __half2 h = __floats2half2_rn(v0, v1);
    return *(uint32_t*)&h;
}

// ---------------------------------------------------------------------------
// Prep: fp32 [M,1024] -> fp16 hi into xe cols 0-1023 (rows stride 2048)
// ---------------------------------------------------------------------------
__global__ void convert_a_kernel(const float* __restrict__ X,
                                 __half* __restrict__ Xe)
{
    int idx = blockIdx.x * 256 + threadIdx.x;
    int m  = idx >> 8;
    int c4 = (idx & 255) * 4;
    float4 v = *(const float4*)&X[(size_t)m * CC + c4];
    uint32_t h01 = pack_h2(v.x, v.y);
    uint32_t h23 = pack_h2(v.z, v.w);
    *(uint2*)&Xe[(size_t)m * KEXT + c4] = make_uint2(h01, h23);
}

// ---------------------------------------------------------------------------
// Prep (fused x4): W[K,N] fp32 -> We[N,2048] fp16 = [Wh | Wh] (transposed)
// ---------------------------------------------------------------------------
__global__ void convert_w4_kernel(const float* __restrict__ W0,
                                  const float* __restrict__ W1,
                                  const float* __restrict__ W2,
                                  const float* __restrict__ W3,
                                  __half* __restrict__ We)
{
    __shared__ float tile[32][33];
    const float* W = (blockIdx.z == 0) ? W0 : (blockIdx.z == 1) ? W1
                   : (blockIdx.z == 2) ? W2 : W3;
    __half* dst = We + (size_t)blockIdx.z * CC * KEXT;
    int n0 = blockIdx.x * 32, k0 = blockIdx.y * 32;
    int tx = threadIdx.x, ty = threadIdx.y;
#pragma unroll
    for (int r = 0; r < 4; r++)
        tile[ty + 8*r][tx] = W[(size_t)(k0 + ty + 8*r) * CC + n0 + tx];
    __syncthreads();
#pragma unroll
    for (int r = 0; r < 4; r++) {
        int n = n0 + ty + 8*r;
        int k = k0 + tx;
        __half h = __float2half(tile[tx][ty + 8*r]);
        size_t base = (size_t)n * KEXT;
        dst[base + k]        = h;
        dst[base + 1024 + k] = h;
    }
}

// ---------------------------------------------------------------------------
// GEMM machinery: 64x128 tile, 128 threads (4 warps, 2m x 2n, warp 32x64),
// K-chunk 64, 2-stage cp.async pipeline. 4 CTA/SM.
// ---------------------------------------------------------------------------
#define GROWB 144                        // smem row bytes (64 fp16 + 8 pad)
#define A_BYTES (64 * GROWB)             // 9216 (A: 64 rows)
#define B_BYTES (128 * GROWB)            // 18432 (B: 128 rows)
#define GBUF (A_BYTES + B_BYTES)         // 27648 per stage
#define GSMEM (2 * GBUF)                 // 55296

struct GemmCtx {
    uint32_t sbase;
    int tid, wid, lane, wm, wn;
    uint32_t a_row, a_col, b_row, b_col;
};
__device__ __forceinline__ void gemm_init(GemmCtx& g, uint32_t sbase) {
    g.tid = threadIdx.x; g.wid = g.tid >> 5; g.lane = g.tid & 31;
    g.sbase = sbase;
    g.wm = (g.wid >> 1) * 32; g.wn = (g.wid & 1) * 64;
    g.a_row = g.wm + (g.lane & 15);
    g.a_col = (g.lane >> 4) * 8;
    g.b_row = g.wn + (g.lane & 7) + ((g.lane >> 4) << 3);
    g.b_col = ((g.lane >> 3) & 1) * 8;
}
__device__ __forceinline__ void gemm_issue(const GemmCtx& g, int it,
                                           const __half* A, const __half* B,
                                           int m0, int n0) {
    const int kc = it * 64;
    const uint32_t buf = g.sbase + (it & 1) * GBUF;
    // A: 64 rows x 8 chunks = 512 over 128 threads
#pragma unroll
    for (int i = 0; i < 4; i++) {
        int idx = g.tid + 128 * i;
        int row = idx >> 3, c = idx & 7;
        cp_async16(buf + row * GROWB + c * 16,
                   A + (size_t)(m0 + row) * KEXT + kc + c * 8);
    }
    // B: 128 rows x 8 chunks = 1024 over 128 threads
#pragma unroll
    for (int i = 0; i < 8; i++) {
        int idx = g.tid + 128 * i;
        int row = idx >> 3, c = idx & 7;
        cp_async16(buf + A_BYTES + row * GROWB + c * 16,
                   B + (size_t)(n0 + row) * KEXT + kc + c * 8);
    }
    CP_COMMIT();
}
__device__ __forceinline__ void gemm_step(const GemmCtx& g, int it, float acc[2][8][4]) {
    const uint32_t buf = g.sbase + (it & 1) * GBUF;
    const uint32_t bufB = buf + A_BYTES;
#pragma unroll
    for (int ki = 0; ki < 4; ki++) {
        uint32_t a[2][4];
#pragma unroll
        for (int mi = 0; mi < 2; mi++) {
            uint32_t addr = buf + (g.a_row + mi*16) * GROWB + (ki*16 + g.a_col) * 2;
            ldm_x4(addr, a[mi][0], a[mi][1], a[mi][2], a[mi][3]);
        }
        uint32_t b[8][2];
#pragma unroll
        for (int nj = 0; nj < 4; nj++) {
            uint32_t addr = bufB + (g.b_row + nj*16) * GROWB + (ki*16 + g.b_col) * 2;
            uint32_t r0, r1, r2, r3;
            ldm_x4(addr, r0, r1, r2, r3);
            b[2*nj  ][0] = r0; b[2*nj  ][1] = r1;
            b[2*nj+1][0] = r2; b[2*nj+1][1] = r3;
        }
#pragma unroll
        for (int mi = 0; mi < 2; mi++)
#pragma unroll
            for (int nj = 0; nj < 8; nj++)
                mma16816(acc[mi][nj], a[mi], b[nj][0], b[nj][1]);
    }
}

// ---------------------------------------------------------------------------
// Fused QKV projection: K=1024 (hi-only A, Wh half of We). Tile 64x128.
// ---------------------------------------------------------------------------
__global__ __launch_bounds__(128, 4)
void gemm_qkv_kernel(const __half* __restrict__ Ae,
                     const __half* __restrict__ We,
                     const float* __restrict__ bq,
                     const float* __restrict__ bk,
                     const float* __restrict__ bv,
                     __half* __restrict__ qe,
                     __half* __restrict__ ke,
                     __half* __restrict__ ve)
{
    extern __shared__ __align__(16) char smem[];
    const int z = blockIdx.z;
    const __half* Be = We + (size_t)z * CC * KEXT;
    const float* bias = (z == 0) ? bq : (z == 1) ? bk : bv;
    __half* out = (z == 0) ? qe : (z == 1) ? ke : ve;
    const float escale = (z == 0) ? 0.125f * 1.44269504f : 1.0f;
    const int m0 = blockIdx.y * 64, n0 = blockIdx.x * 128;

    GemmCtx g; gemm_init(g, smem_to_u32(smem));
    float acc[2][8][4];
#pragma unroll
    for (int i = 0; i < 2; i++)
#pragma unroll
        for (int j = 0; j < 8; j++)
#pragma unroll
            for (int k = 0; k < 4; k++) acc[i][j][k] = 0.f;

    gemm_issue(g, 0, Ae, Be, m0, n0);
    for (int it = 0; it < NITQ; it++) {
        if (it + 1 < NITQ) { gemm_issue(g, it + 1, Ae, Be, m0, n0); CP_WAIT(1); }
        else               { CP_WAIT(0); }
        __syncthreads();
        gemm_step(g, it, acc);
        __syncthreads();
    }

    const int erow = m0 + g.wm + (g.lane >> 2);
    const int ecol0 = n0 + g.wn + 2 * (g.lane & 3);
#pragma unroll
    for (int mi = 0; mi < 2; mi++)
#pragma unroll
        for (int nj = 0; nj < 8; nj++) {
            int col = ecol0 + nj * 8;
            float bx = bias[col], by = bias[col + 1];
            int r0 = erow + mi * 16;
            int b_ = r0 >> 11, t = r0 & 2047;
            int h  = col >> 6, d = col & 63;
            __half* base = out + ((size_t)((b_ << 4) + h) * TT + t) * 64 + d;
            *(uint32_t*)base =
                pack_h2((acc[mi][nj][0] + bx) * escale, (acc[mi][nj][1] + by) * escale);
            *(uint32_t*)(base + 512) =
                pack_h2((acc[mi][nj][2] + bx) * escale, (acc[mi][nj][3] + by) * escale);
        }
}

// ---------------------------------------------------------------------------
// Output projection: K=1024 (oh only), fp32 out. Tile 64x128.
// ---------------------------------------------------------------------------
__global__ __launch_bounds__(128, 4)
void gemm_out_kernel(const __half* __restrict__ Ae,
                     const __half* __restrict__ Be,
                     const float* __restrict__ bias,
                     float* __restrict__ Cout)
{
    extern __shared__ __align__(16) char smem[];
    const int m0 = blockIdx.y * 64, n0 = blockIdx.x * 128;

    GemmCtx g; gemm_init(g, smem_to_u32(smem));
    float acc[2][8][4];
#pragma unroll
    for (int i = 0; i < 2; i++)
#pragma unroll
        for (int j = 0; j < 8; j++)
#pragma unroll
            for (int k = 0; k < 4; k++) acc[i][j][k] = 0.f;

    gemm_issue(g, 0, Ae, Be, m0, n0);
    for (int it = 0; it < NIT; it++) {
        if (it + 1 < NIT) { gemm_issue(g, it + 1, Ae, Be, m0, n0); CP_WAIT(1); }
        else              { CP_WAIT(0); }
        __syncthreads();
        gemm_step(g, it, acc);
        __syncthreads();
    }

    const int erow = m0 + g.wm + (g.lane >> 2);
    const int ecol0 = n0 + g.wn + 2 * (g.lane & 3);
#pragma unroll
    for (int mi = 0; mi < 2; mi++)
#pragma unroll
        for (int nj = 0; nj < 8; nj++) {
            int col = ecol0 + nj * 8;
            float bx = bias[col], by = bias[col + 1];
            int r0 = erow + mi * 16;
            *(float2*)&Cout[(size_t)r0 * CC + col] =
                make_float2(acc[mi][nj][0] + bx, acc[mi][nj][1] + by);
            *(float2*)&Cout[(size_t)(r0 + 8) * CC + col] =
                make_float2(acc[mi][nj][2] + bx, acc[mi][nj][3] + by);
        }
}

// ---------------------------------------------------------------------------
// MMA flash attention (R16 proven): 64-row Q tile, 4 warps x 16 rows, 4 CTA/SM.
// grid (T/64, B*H), 128 threads.
// ---------------------------------------------------------------------------
#define KSTR2 144                 // Q/K/V smem row stride bytes (64 fp16 + pad)
#define ATQ_SZ (64 * KSTR2)       // 9216 (persistent Q tile, 64 rows)
#define AT_VOFF (64 * KSTR2)      // 9216
#define AT_BUF  (2 * 64 * KSTR2)  // 18432 per KV buffer
#define AT_SMEM (ATQ_SZ + 2 * AT_BUF)  // 46080 (dynamic)

__global__ __launch_bounds__(128, 4)
void attn_mma_kernel(const __half* __restrict__ Qe,
                     const __half* __restrict__ Ke,
                     const __half* __restrict__ Ve,
                     __half* __restrict__ oe)
{
    extern __shared__ __align__(16) char smem[];
    const uint32_t sbase = smem_to_u32(smem);
    const uint32_t kvbase = sbase + ATQ_SZ;
    const int tid  = threadIdx.x;
    const int wid  = tid >> 5;
    const int lane = tid & 31;
    const int qb   = blockIdx.x;
    const int bh   = blockIdx.y;
    const int wm   = wid * 16;

    const __half* Qg = Qe + ((size_t)bh * TT + qb * 64) * 64;
    const __half* Kg = Ke + (size_t)bh * TT * 64;
    const __half* Vg = Ve + (size_t)bh * TT * 64;

#pragma unroll
    for (int i = 0; i < 4; i++) {
        int idx = tid + 128 * i;
        int row = idx >> 3, c = idx & 7;
        cp_async16(sbase + row * KSTR2 + c * 16, Qg + (size_t)row * 64 + c * 8);
    }
    CP_COMMIT();

    auto issue = [&](int kt) {
        const uint32_t buf = kvbase + (kt & 1) * AT_BUF;
        const int r0 = kt * 64;
#pragma unroll
        for (int i = 0; i < 4; i++) {
            int idx = tid + 128 * i;
            int row = idx >> 3, c = idx & 7;
            cp_async16(buf + row * KSTR2 + c * 16, Kg + (size_t)(r0 + row) * 64 + c * 8);
            cp_async16(buf + AT_VOFF + row * KSTR2 + c * 16, Vg + (size_t)(r0 + row) * 64 + c * 8);
        }
        CP_COMMIT();
    };

    issue(0);
    CP_WAIT(1);
    __syncthreads();

    uint32_t aq[4][4];
    {
        const uint32_t qfrag = sbase + (wm + (lane & 15)) * KSTR2 + ((lane >> 4) * 8) * 2;
#pragma unroll
        for (int c = 0; c < 4; c++)
            ldm_x4(qfrag + c * 32, aq[c][0], aq[c][1], aq[c][2], aq[c][3]);
    }

    float oacc[8][4];
#pragma unroll
    for (int j = 0; j < 8; j++)
#pragma unroll
        for (int k = 0; k < 4; k++) oacc[j][k] = 0.f;
    float lsum0 = 0.f, lsum1 = 0.f;

    const uint32_t frow_off = ((lane & 7) + ((lane >> 3) & 1) * 8) * KSTR2;
    const uint32_t fcol_off = ((lane >> 4) * 8) * 2;

    for (int it = 0; it < TT / 64; it++) {
        if (it + 1 < TT / 64) { issue(it + 1); CP_WAIT(1); }
        else                  { CP_WAIT(0); }
        __syncthreads();
        const uint32_t kb = kvbase + (it & 1) * AT_BUF + frow_off + fcol_off;
        const uint32_t vb = kb + AT_VOFF;

        float s[8][4];
#pragma unroll
        for (int j = 0; j < 8; j++)
#pragma unroll
            for (int k = 0; k < 4; k++) s[j][k] = 0.f;

#pragma unroll
        for (int g = 0; g < 4; g++) {
            uint32_t grow = kb + g * (16 * KSTR2);
#pragma unroll
            for (int c = 0; c < 4; c++) {
                uint32_t r0, r1, r2, r3;
                ldm_x4(grow + c * 32, r0, r1, r2, r3);
                mma16816(s[2*g],   aq[c], r0, r2);
                mma16816(s[2*g+1], aq[c], r1, r3);
            }
        }

        uint32_t ph[4][4];
#pragma unroll
        for (int g = 0; g < 4; g++) {
            float e0 = ex2f(s[2*g][0]),   e1 = ex2f(s[2*g][1]);
            float e2 = ex2f(s[2*g][2]),   e3 = ex2f(s[2*g][3]);
            float e4 = ex2f(s[2*g+1][0]), e5 = ex2f(s[2*g+1][1]);
            float e6 = ex2f(s[2*g+1][2]), e7 = ex2f(s[2*g+1][3]);
            lsum0 += e0 + e1 + e4 + e5;
            lsum1 += e2 + e3 + e6 + e7;
            ph[g][0] = pack_h2(e0, e1);
            ph[g][1] = pack_h2(e2, e3);
            ph[g][2] = pack_h2(e4, e5);
            ph[g][3] = pack_h2(e6, e7);
        }

#pragma unroll
        for (int g = 0; g < 4; g++) {
            uint32_t vrb = vb + g * (16 * KSTR2);
#pragma unroll
            for (int ng = 0; ng < 4; ng++) {
                uint32_t r0, r1, r2, r3;
                ldm_x4_t(vrb + ng * 32, r0, r1, r2, r3);
                mma16816(oacc[2*ng],   ph[g], r0, r1);
                mma16816(oacc[2*ng+1], ph[g], r2, r3);
            }
        }
        __syncthreads();
    }

    lsum0 += __shfl_xor_sync(0xFFFFFFFF, lsum0, 1);
    lsum0 += __shfl_xor_sync(0xFFFFFFFF, lsum0, 2);
    lsum1 += __shfl_xor_sync(0xFFFFFFFF, lsum1, 1);
    lsum1 += __shfl_xor_sync(0xFFFFFFFF, lsum1, 2);
    float inv0 = 1.f / lsum0, inv1 = 1.f / lsum1;

    int b_ = bh >> 4, h = bh & 15;
    int t0 = qb * 64 + wm + (lane >> 2);
    size_t m = (size_t)b_ * TT + t0;
    int colb = h * 64 + 2 * (lane & 3);
#pragma unroll
    for (int nj = 0; nj < 8; nj++) {
        int col = colb + nj * 8;
        __half* base = oe + m * KEXT + col;
        *(uint32_t*)base = pack_h2(oacc[nj][0] * inv0, oacc[nj][1] * inv0);
        *(uint32_t*)(base + 8 * KEXT) = pack_h2(oacc[nj][2] * inv1, oacc[nj][3] * inv1);
    }
}

// ---------------------------------------------------------------------------
extern "C" void kernel_launch(void* const* d_in, const int* in_sizes, int n_in,
                              void* d_out, int out_size)
{
    const float* x  = (const float*)d_in[0];
    const float* Wq = (const float*)d_in[2];
    const float* bq = (const float*)d_in[3];
    const float* Wk = (const float*)d_in[4];
    const float* bk = (const float*)d_in[5];
    const float* Wv = (const float*)d_in[6];
    const float* bv = (const float*)d_in[7];
    const float* Wp = (const float*)d_in[8];
    const float* bp = (const float*)d_in[9];
    float* out = (float*)d_out;

    __half *xe, *we, *qe, *ke, *ve;
    cudaGetSymbolAddress((void**)&xe, g_xe);
    cudaGetSymbolAddress((void**)&we, g_We);
    cudaGetSymbolAddress((void**)&qe, g_Qe);
    cudaGetSymbolAddress((void**)&ke, g_Ke);
    cudaGetSymbolAddress((void**)&ve, g_Ve);
    __half* wpe = we + (size_t)3 * CC * KEXT;

    cudaFuncSetAttribute(gemm_qkv_kernel,
                         cudaFuncAttributeMaxDynamicSharedMemorySize, GSMEM);
    cudaFuncSetAttribute(gemm_out_kernel,
                         cudaFuncAttributeMaxDynamicSharedMemorySize, GSMEM);
    cudaFuncSetAttribute(attn_mma_kernel,
                         cudaFuncAttributeMaxDynamicSharedMemorySize, AT_SMEM);

    // prep
    convert_a_kernel<<<MM, 256>>>(x, xe);
    dim3 wgrd(CC / 32, CC / 32, 4), wblk(32, 8);
    convert_w4_kernel<<<wgrd, wblk>>>(Wq, Wk, Wv, Wp, we);

    // fused QKV projections (K=1024, hi-only), 64x128 tiles
    dim3 qgrd(CC / 128, MM / 64, 3);   // (8, 64, 3) = 1536 CTAs
    gemm_qkv_kernel<<<qgrd, 128, GSMEM>>>(xe, we, bq, bk, bv, qe, ke, ve);

    // attention (writes oh into xe cols 0-1023)
    dim3 agrd(TT / 64, BB * HH);       // (32, 32) = 1024 CTAs
    attn_mma_kernel<<<agrd, 128, AT_SMEM>>>(qe, ke, ve, xe);

    // output projection (K=1024, oh only), 64x128 tiles
    dim3 ggrd(CC / 128, MM / 64);      // (8, 64) = 512 CTAs
    gemm_out_kernel<<<ggrd, 128, GSMEM>>>(xe, wpe, bp, out);
}